// round 2
// baseline (speedup 1.0000x reference)
#include <cuda_runtime.h>
#include <math.h>

#define B_    2
#define H_    8
#define G_    2
#define HPG   4
#define DH    64
#define BLK   64
#define TOPK  2
#define DIM   512
#define NPB   2048
#define NTOT  4096
#define W_    32
#define CH    4096
#define QKVN  768

// ---------------- scratch layout (floats) ----------------
#define OFF_INP     0ul
#define OFF_QKV     2097152ul
#define OFF_Q       5242880ul
#define OFF_K       7340032ul
#define OFF_KR      7864320ul
#define OFF_V       8388608ul
#define OFF_KBM     8912896ul
#define OFF_VBM     9437184ul
#define OFF_KHID    9961472ul
#define OFF_VHID   10485760ul
#define OFF_CKRAW  11010048ul
#define OFF_CVRAW  11018240ul
#define OFF_CK     11026432ul
#define OFF_CV     11034880ul
#define OFF_COUT   11043328ul
#define OFF_FOUT   13140480ul
#define OFF_SOUT   15237632ul
#define OFF_IMP    17334784ul
#define OFF_SELVAL 17596928ul
#define OFF_GATES  17613312ul
#define OFF_COMB   17711616ul
#define OFF_PM     19808768ul
#define SCRATCH_SZ 19808960ul

__device__ float g_scratch[SCRATCH_SZ];
__device__ int   g_selidx[2 * 2 * 2048 * 2];

// ---------------- pos block means ----------------
__global__ void k_posmean(const float* __restrict__ pos) {
    int blk = blockIdx.x;          // 64 blocks of 64 rows
    int t = threadIdx.x;           // 64
    __shared__ float s[64 * 3];
    s[t * 3 + 0] = pos[(blk * 64 + t) * 3 + 0];
    s[t * 3 + 1] = pos[(blk * 64 + t) * 3 + 1];
    s[t * 3 + 2] = pos[(blk * 64 + t) * 3 + 2];
    __syncthreads();
    if (t < 3) {
        float sum = 0.f;
        for (int i = 0; i < 64; i++) sum += s[i * 3 + t];
        g_scratch[OFF_PM + blk * 3 + t] = sum / 64.f;
    }
}

// ---------------- PE add + RMSNorm ----------------
__global__ void k_pe_norm(const float* __restrict__ x, const float* __restrict__ pos,
                          const float* __restrict__ peW, const float* __restrict__ peb,
                          const float* __restrict__ nsc) {
    int r = blockIdx.x;            // 4096 rows
    int t = threadIdx.x;           // 256
    int blk = r >> 6;
    float r0 = pos[r * 3 + 0] - g_scratch[OFF_PM + blk * 3 + 0];
    float r1 = pos[r * 3 + 1] - g_scratch[OFF_PM + blk * 3 + 1];
    float r2 = pos[r * 3 + 2] - g_scratch[OFF_PM + blk * 3 + 2];
    int c0 = t, c1 = t + 256;
    float v0 = x[(size_t)r * 512 + c0] + r0 * peW[c0] + r1 * peW[512 + c0] + r2 * peW[1024 + c0] + peb[c0];
    float v1 = x[(size_t)r * 512 + c1] + r0 * peW[c1] + r1 * peW[512 + c1] + r2 * peW[1024 + c1] + peb[c1];
    __shared__ float red[256];
    red[t] = v0 * v0 + v1 * v1;
    __syncthreads();
    for (int s = 128; s > 0; s >>= 1) {
        if (t < s) red[t] += red[t + s];
        __syncthreads();
    }
    float rms = rsqrtf(red[0] / 512.f + 1e-6f);
    g_scratch[OFF_INP + (size_t)r * 512 + c0] = v0 * rms * nsc[c0];
    g_scratch[OFF_INP + (size_t)r * 512 + c1] = v1 * rms * nsc[c1];
}

// ---------------- generic SGEMM: C = A(MxK) @ B(KxN) + bias, optional relu ----------------
__global__ void sgemm(const float* __restrict__ A, const float* __restrict__ B,
                      const float* __restrict__ bias, float* __restrict__ C,
                      int M, int N, int K, int relu) {
    __shared__ float As[16][64];
    __shared__ float Bs[16][64];
    int bx = blockIdx.x, by = blockIdx.y;
    int tid = threadIdx.x;
    int tx = tid & 15, ty = tid >> 4;
    float acc[4][4];
#pragma unroll
    for (int i = 0; i < 4; i++)
#pragma unroll
        for (int j = 0; j < 4; j++) acc[i][j] = 0.f;
    const float* Ab = A + (size_t)by * 64 * K;
    const float* Bb = B + (size_t)bx * 64;
    for (int k0 = 0; k0 < K; k0 += 16) {
#pragma unroll
        for (int u = 0; u < 4; u++) {
            int idx = tid * 4 + u;
            int r = idx >> 4, c = idx & 15;
            As[c][r] = Ab[(size_t)r * K + k0 + c];
        }
#pragma unroll
        for (int u = 0; u < 4; u++) {
            int idx = tid + u * 256;
            int r = idx >> 6, c = idx & 63;
            Bs[r][c] = Bb[(size_t)(k0 + r) * N + c];
        }
        __syncthreads();
#pragma unroll
        for (int kk = 0; kk < 16; kk++) {
            float a[4], b[4];
#pragma unroll
            for (int i = 0; i < 4; i++) a[i] = As[kk][ty * 4 + i];
#pragma unroll
            for (int j = 0; j < 4; j++) b[j] = Bs[kk][tx * 4 + j];
#pragma unroll
            for (int i = 0; i < 4; i++)
#pragma unroll
                for (int j = 0; j < 4; j++) acc[i][j] += a[i] * b[j];
        }
        __syncthreads();
    }
#pragma unroll
    for (int i = 0; i < 4; i++)
#pragma unroll
        for (int j = 0; j < 4; j++) {
            int row = by * 64 + ty * 4 + i;
            int col = bx * 64 + tx * 4 + j;
            float v = acc[i][j] + (bias ? bias[col] : 0.f);
            if (relu) v = fmaxf(v, 0.f);
            C[(size_t)row * N + col] = v;
        }
}

// ---------------- split qkv + rope ----------------
__global__ void k_split_rope() {
    int r = blockIdx.x;           // 4096
    int b = r >> 11;
    int i = r & 2047;
    int t = threadIdx.x;          // 384
    const float* qkv = g_scratch + OFF_QKV + (size_t)r * 768;
    if (t < 256) {
        int col = t * 2;
        int head = col >> 6, d = col & 63, j = d >> 1;
        float inv = powf(10000.f, -(float)j / 32.f);
        float cs, sn;
        sincosf((float)i * inv, &sn, &cs);
        float a = qkv[col], bb = qkv[col + 1];
        float o0 = a * cs - bb * sn;
        float o1 = bb * cs + a * sn;
        size_t base = (((size_t)(b * 8 + head) * 2048 + i) * 64 + d);
        g_scratch[OFF_Q + base] = o0;
        g_scratch[OFF_Q + base + 1] = o1;
    } else if (t < 320) {
        int ci = (t - 256) * 2;
        int g = ci >> 6, d = ci & 63, j = d >> 1;
        float inv = powf(10000.f, -(float)j / 32.f);
        float cs, sn;
        sincosf((float)i * inv, &sn, &cs);
        float a = qkv[512 + ci], bb = qkv[512 + ci + 1];
        size_t base = (((size_t)(b * 2 + g) * 2048 + i) * 64 + d);
        g_scratch[OFF_K + base] = a;
        g_scratch[OFF_K + base + 1] = bb;
        g_scratch[OFF_KR + base] = a * cs - bb * sn;
        g_scratch[OFF_KR + base + 1] = bb * cs + a * sn;
    } else {
        int ci = (t - 320) * 2;
        int g = ci >> 6, d = ci & 63;
        size_t base = (((size_t)(b * 2 + g) * 2048 + i) * 64 + d);
        g_scratch[OFF_V + base] = qkv[640 + ci];
        g_scratch[OFF_V + base + 1] = qkv[640 + ci + 1];
    }
}

// ---------------- build compressor input matrices ----------------
__global__ void k_buildmats(const float* __restrict__ k_pos, const float* __restrict__ v_pos) {
    int idx = blockIdx.x * blockDim.x + threadIdx.x;
    if (idx >= 128 * 4096) return;
    int row = idx >> 12, col = idx & 4095;
    int bg = row >> 5, wi = row & 31, g = bg & 1;
    int j = col >> 6, d = col & 63;
    size_t src = ((size_t)bg * 2048 + wi * 64 + j) * 64 + d;
    float pk = k_pos[(g * 64 + j) * 64 + d];
    float pv = v_pos[(g * 64 + j) * 64 + d];
    g_scratch[OFF_KBM + idx] = g_scratch[OFF_K + src] + pk;
    g_scratch[OFF_VBM + idx] = g_scratch[OFF_V + src] + pv;
}

// ---------------- pack ck/cv with mem token ----------------
__global__ void k_pack(const float* __restrict__ mem_k, const float* __restrict__ mem_v) {
    int idx = blockIdx.x * blockDim.x + threadIdx.x;
    if (idx >= 2 * 2 * 33 * 64) return;
    int d = idx & 63;
    int rest = idx >> 6;
    int j = rest % 33;
    int bg = rest / 33;
    int g = bg & 1;
    float kv, vv;
    if (j == 0) {
        kv = mem_k[g * 64 + d];
        vv = mem_v[g * 64 + d];
    } else {
        size_t s = ((size_t)bg * 32 + (j - 1)) * 64 + d;
        kv = g_scratch[OFF_CKRAW + s];
        vv = g_scratch[OFF_CVRAW + s];
    }
    g_scratch[OFF_CK + idx] = kv;
    g_scratch[OFF_CV + idx] = vv;
}

// ---------------- coarse attention + importance ----------------
__global__ void k_coarse() {
    int bi = blockIdx.x;          // 8192 = bg*2048 + i
    int bg = bi >> 11, i = bi & 2047;
    int b = bg >> 1, g = bg & 1;
    int t = threadIdx.x;          // 128
    __shared__ float sck[33 * 64], scv[33 * 64], sq[4 * 64], sp[4 * 33];
    for (int u = t; u < 33 * 64; u += 128) {
        sck[u] = g_scratch[OFF_CK + (size_t)bg * 2112 + u];
        scv[u] = g_scratch[OFF_CV + (size_t)bg * 2112 + u];
    }
    for (int u = t; u < 256; u += 128) {
        int hq = u >> 6, d = u & 63;
        sq[u] = g_scratch[OFF_Q + (((size_t)(b * 8 + g * 4 + hq) * 2048 + i) * 64 + d)];
    }
    __syncthreads();
    for (int u = t; u < 132; u += 128) {
        int hq = u / 33, j = u % 33;
        float s = -1e30f;
        if (j == 0 || j * 64 <= i) {
            float acc = 0.f;
            for (int d = 0; d < 64; d++) acc += sq[hq * 64 + d] * sck[j * 64 + d];
            s = acc * 0.125f;
        }
        sp[u] = s;
    }
    __syncthreads();
    if (t < 4) {
        float m = -1e30f;
        for (int j = 0; j < 33; j++) m = fmaxf(m, sp[t * 33 + j]);
        float sum = 0.f;
        for (int j = 0; j < 33; j++) {
            float e = expf(sp[t * 33 + j] - m);
            sp[t * 33 + j] = e;
            sum += e;
        }
        float inv = 1.f / sum;
        for (int j = 0; j < 33; j++) sp[t * 33 + j] *= inv;
    }
    __syncthreads();
    if (t < 32) {
        g_scratch[OFF_IMP + ((size_t)bg * 2048 + i) * 32 + t] =
            0.25f * (sp[t + 1] + sp[33 + t + 1] + sp[66 + t + 1] + sp[99 + t + 1]);
    }
    for (int u = t; u < 256; u += 128) {
        int hq = u >> 6, d = u & 63;
        float acc = 0.f;
        for (int j = 0; j < 33; j++) acc += sp[hq * 33 + j] * scv[j * 64 + d];
        g_scratch[OFF_COUT + (((size_t)(b * 8 + g * 4 + hq) * 2048 + i) * 64 + d)] = acc;
    }
}

// ---------------- top-k (k=2, stable) ----------------
__global__ void k_topk() {
    int idx = blockIdx.x * blockDim.x + threadIdx.x;
    if (idx >= 8192) return;
    const float* imp = g_scratch + OFF_IMP + (size_t)idx * 32;
    int i1 = 0;
    float v1 = imp[0];
    for (int j = 1; j < 32; j++)
        if (imp[j] > v1) { v1 = imp[j]; i1 = j; }
    int i2 = -1;
    float v2 = -1e30f;
    for (int j = 0; j < 32; j++) {
        if (j == i1) continue;
        if (imp[j] > v2) { v2 = imp[j]; i2 = j; }
    }
    g_scratch[OFF_SELVAL + idx * 2 + 0] = v1;
    g_scratch[OFF_SELVAL + idx * 2 + 1] = v2;
    g_selidx[idx * 2 + 0] = i1;
    g_selidx[idx * 2 + 1] = i2;
}

// ---------------- fine gathered attention ----------------
#define FINE_SMEM ((192 * 64 * 2 + 256 + 768) * 4)
extern __shared__ float fsm[];
__global__ void k_fine() {
    float* sk = fsm;              // 192*64
    float* sv = fsm + 12288;      // 192*64
    float* sq = fsm + 24576;      // 256
    float* sp = fsm + 24832;      // 4*192
    int bi = blockIdx.x;
    int bg = bi >> 11, i = bi & 2047;
    int b = bg >> 1, g = bg & 1;
    int t = threadIdx.x;          // 256
    int own = i >> 6;
    __shared__ int blkid[3];
    __shared__ int okf[3];
    if (t < 2) {
        int si = g_selidx[bi * 2 + t];
        float sval = g_scratch[OFF_SELVAL + bi * 2 + t];
        blkid[t] = si;
        okf[t] = (sval > 0.f && si != own) ? 1 : 0;
    }
    if (t == 2) { blkid[2] = own; okf[2] = 1; }
    __syncthreads();
    size_t kbase = (size_t)bg * 2048 * 64;
    for (int u = t; u < 12288; u += 256) {
        int kk = u >> 6, d = u & 63;
        int kb = kk >> 6, j = kk & 63;
        size_t src = kbase + (size_t)(blkid[kb] * 64 + j) * 64 + d;
        sk[u] = g_scratch[OFF_KR + src];
        sv[u] = g_scratch[OFF_V + src];
    }
    if (t < 256) {
        int hq = t >> 6, d = t & 63;
        sq[t] = g_scratch[OFF_Q + (((size_t)(b * 8 + g * 4 + hq) * 2048 + i) * 64 + d)];
    }
    __syncthreads();
    int ilocal = i & 63;
    for (int u = t; u < 768; u += 256) {
        int hq = u / 192, kk = u % 192;
        int kb = kk >> 6, j = kk & 63;
        bool valid = (kb < 2) ? (okf[kb] != 0) : (j <= ilocal);
        float s = -1e30f;
        if (valid) {
            float acc = 0.f;
            for (int d = 0; d < 64; d++) acc += sq[hq * 64 + d] * sk[kk * 64 + d];
            s = acc * 0.125f;
        }
        sp[u] = s;
    }
    __syncthreads();
    int w = t >> 5, lane = t & 31;
    if (w < 4) {
        float m = -1e30f;
        for (int kk = lane; kk < 192; kk += 32) m = fmaxf(m, sp[w * 192 + kk]);
        for (int o = 16; o; o >>= 1) m = fmaxf(m, __shfl_xor_sync(~0u, m, o));
        float sum = 0.f;
        for (int kk = lane; kk < 192; kk += 32) {
            float e = expf(sp[w * 192 + kk] - m);
            sp[w * 192 + kk] = e;
            sum += e;
        }
        for (int o = 16; o; o >>= 1) sum += __shfl_xor_sync(~0u, sum, o);
        float inv = 1.f / sum;
        for (int kk = lane; kk < 192; kk += 32) sp[w * 192 + kk] *= inv;
    }
    __syncthreads();
    {
        int hq = t >> 6, d = t & 63;
        float acc = 0.f;
        for (int kk = 0; kk < 192; kk++) acc += sp[hq * 192 + kk] * sv[kk * 64 + d];
        g_scratch[OFF_FOUT + (((size_t)(b * 8 + g * 4 + hq) * 2048 + i) * 64 + d)] = acc;
    }
}

// ---------------- sliding (256-wide full) attention ----------------
#define SLIDE_SMEM ((16448 + 16384 + 4096) * 4)
extern __shared__ float ssm[];
__global__ void k_slide() {
    float* sK = ssm;              // 64*257 (transposed K) / reused as V[256*64]
    float* sS = ssm + 16448;      // 64*256
    float* sQ = ssm + 32832;      // 64*64
    int id = blockIdx.x;          // ((b*8+hh)*8 + tile)*4 + qc
    int qc = id & 3;
    int tile = (id >> 2) & 7;
    int hh = (id >> 5) & 7;
    int b = id >> 8;
    int g = hh >> 2;
    int t = threadIdx.x;          // 256
    size_t kbase = ((size_t)(b * 2 + g) * 2048 + (size_t)tile * 256) * 64;
    size_t qbase = (((size_t)(b * 8 + hh) * 2048) + tile * 256 + qc * 64) * 64;
    for (int u = t; u < 16384; u += 256) {
        int kk = u >> 6, d = u & 63;
        sK[d * 257 + kk] = g_scratch[OFF_KR + kbase + u];
    }
    for (int u = t; u < 4096; u += 256) sQ[u] = g_scratch[OFF_Q + qbase + u];
    __syncthreads();
    for (int u = t; u < 16384; u += 256) {
        int q = u >> 8, kk = u & 255;
        float acc = 0.f;
        for (int d = 0; d < 64; d++) acc += sQ[q * 64 + d] * sK[d * 257 + kk];
        sS[u] = acc * 0.125f;
    }
    __syncthreads();
    int w = t >> 5, lane = t & 31;
    for (int q = w; q < 64; q += 8) {
        float m = -1e30f;
        for (int kk = lane; kk < 256; kk += 32) m = fmaxf(m, sS[q * 256 + kk]);
        for (int o = 16; o; o >>= 1) m = fmaxf(m, __shfl_xor_sync(~0u, m, o));
        float sum = 0.f;
        for (int kk = lane; kk < 256; kk += 32) {
            float e = expf(sS[q * 256 + kk] - m);
            sS[q * 256 + kk] = e;
            sum += e;
        }
        for (int o = 16; o; o >>= 1) sum += __shfl_xor_sync(~0u, sum, o);
        float inv = 1.f / sum;
        for (int kk = lane; kk < 256; kk += 32) sS[q * 256 + kk] *= inv;
    }
    __syncthreads();
    for (int u = t; u < 16384; u += 256) sK[u] = g_scratch[OFF_V + kbase + u];
    __syncthreads();
    for (int u = t; u < 4096; u += 256) {
        int q = u >> 6, d = u & 63;
        float acc = 0.f;
        for (int kk = 0; kk < 256; kk++) acc += sS[q * 256 + kk] * sK[kk * 64 + d];
        g_scratch[OFF_SOUT + qbase + u] = acc;
    }
}

// ---------------- gates ----------------
__global__ void k_gates(const float* __restrict__ Wg, const float* __restrict__ bgv) {
    int r = blockIdx.x;           // 4096
    int t = threadIdx.x;          // 128
    __shared__ float sx[512];
    for (int u = t; u < 512; u += 128) sx[u] = g_scratch[OFF_INP + (size_t)r * 512 + u];
    __syncthreads();
    int w = t >> 5, lane = t & 31;
    for (int o = w; o < 24; o += 4) {
        float acc = 0.f;
        for (int kk = lane; kk < 512; kk += 32) acc += sx[kk] * Wg[(size_t)kk * 24 + o];
        for (int off = 16; off; off >>= 1) acc += __shfl_xor_sync(~0u, acc, off);
        if (lane == 0)
            g_scratch[OFF_GATES + (size_t)r * 24 + o] = 1.f / (1.f + expf(-(acc + bgv[o])));
    }
}

// ---------------- combine ----------------
__global__ void k_combine() {
    int idx = blockIdx.x * blockDim.x + threadIdx.x;
    if (idx >= 4096 * 512) return;
    int d = idx & 63;
    int hh = (idx >> 6) & 7;
    int ri = idx >> 9;            // b*2048+i
    int b = ri >> 11, i = ri & 2047;
    size_t hidx = (((size_t)(b * 8 + hh) * 2048 + i) * 64 + d);
    const float* gg = g_scratch + OFF_GATES + (size_t)ri * 24 + hh * 3;
    g_scratch[OFF_COMB + idx] = gg[0] * g_scratch[OFF_COUT + hidx] +
                                gg[1] * g_scratch[OFF_FOUT + hidx] +
                                gg[2] * g_scratch[OFF_SOUT + hidx];
}

// ---------------- host ----------------
extern "C" void kernel_launch(void* const* d_in, const int* in_sizes, int n_in,
                              void* d_out, int out_size) {
    const float* x     = (const float*)d_in[0];
    const float* pos   = (const float*)d_in[1];
    const float* pe_W  = (const float*)d_in[2];
    const float* pe_b  = (const float*)d_in[3];
    const float* nsc   = (const float*)d_in[4];
    const float* Wqkv  = (const float*)d_in[5];
    const float* k_pos = (const float*)d_in[6];
    const float* v_pos = (const float*)d_in[7];
    const float* kcW1  = (const float*)d_in[8];
    const float* kcb1  = (const float*)d_in[9];
    const float* kcW2  = (const float*)d_in[10];
    const float* kcb2  = (const float*)d_in[11];
    const float* vcW1  = (const float*)d_in[12];
    const float* vcb1  = (const float*)d_in[13];
    const float* vcW2  = (const float*)d_in[14];
    const float* vcb2  = (const float*)d_in[15];
    const float* mem_k = (const float*)d_in[16];
    const float* mem_v = (const float*)d_in[17];
    const float* Wg    = (const float*)d_in[18];
    const float* bgv   = (const float*)d_in[19];
    const float* Wo    = (const float*)d_in[20];
    float* out = (float*)d_out;

    float* S = nullptr;
    cudaGetSymbolAddress((void**)&S, g_scratch);

    cudaFuncSetAttribute(k_fine, cudaFuncAttributeMaxDynamicSharedMemorySize, FINE_SMEM);
    cudaFuncSetAttribute(k_slide, cudaFuncAttributeMaxDynamicSharedMemorySize, SLIDE_SMEM);

    k_posmean<<<64, 64>>>(pos);
    k_pe_norm<<<4096, 256>>>(x, pos, pe_W, pe_b, nsc);

    // qkv = inp @ Wqkv
    sgemm<<<dim3(768 / 64, 4096 / 64), 256>>>(S + OFF_INP, Wqkv, nullptr, S + OFF_QKV,
                                              4096, 768, 512, 0);
    k_split_rope<<<4096, 384>>>();
    k_buildmats<<<(128 * 4096 + 255) / 256, 256>>>(k_pos, v_pos);

    // compressors
    sgemm<<<dim3(64, 2), 256>>>(S + OFF_KBM, kcW1, kcb1, S + OFF_KHID, 128, 4096, 4096, 1);
    sgemm<<<dim3(1, 2), 256>>>(S + OFF_KHID, kcW2, kcb2, S + OFF_CKRAW, 128, 64, 4096, 0);
    sgemm<<<dim3(64, 2), 256>>>(S + OFF_VBM, vcW1, vcb1, S + OFF_VHID, 128, 4096, 4096, 1);
    sgemm<<<dim3(1, 2), 256>>>(S + OFF_VHID, vcW2, vcb2, S + OFF_CVRAW, 128, 64, 4096, 0);
    k_pack<<<(8448 + 255) / 256, 256>>>(mem_k, mem_v);

    k_coarse<<<8192, 128>>>();
    k_topk<<<32, 256>>>();
    k_fine<<<8192, 256, FINE_SMEM>>>();
    k_slide<<<512, 256, SLIDE_SMEM>>>();
    k_gates<<<4096, 128>>>(Wg, bgv);
    k_combine<<<(4096 * 512 + 255) / 256, 256>>>();

    // out = comb @ Wo
    sgemm<<<dim3(512 / 64, 4096 / 64), 256>>>(S + OFF_COMB, Wo, nullptr, out,
                                              4096, 512, 512, 0);
}

// round 3
// speedup vs baseline: 1.9646x; 1.9646x over previous
#include <cuda_runtime.h>
#include <math.h>

// ---------------- scratch layout (floats) ----------------
#define OFF_INP     0ul
#define OFF_QKV     2097152ul
#define OFF_Q       5242880ul
#define OFF_K       7340032ul
#define OFF_KR      7864320ul
#define OFF_V       8388608ul
#define OFF_KBM     8912896ul
#define OFF_VBM     9437184ul
#define OFF_KHID    9961472ul
#define OFF_VHID   10485760ul
#define OFF_CKRAW  11010048ul
#define OFF_CVRAW  11018240ul
#define OFF_CK     11026432ul
#define OFF_CV     11034880ul
#define OFF_COUT   11043328ul
#define OFF_FOUT   13140480ul
#define OFF_SOUT   15237632ul
#define OFF_IMP    17334784ul
#define OFF_SELVAL 17596928ul
#define OFF_GATES  17613312ul
#define OFF_COMB   17711616ul
#define OFF_PM     19808768ul
#define OFF_PART   19808960ul   /* 2 comps x 4 chunks x 128 x 4096 */
#define SCRATCH_SZ 24003264ul

__device__ float g_scratch[SCRATCH_SZ];
__device__ int   g_selidx[2 * 2 * 2048 * 2];

// ---------------- pos block means ----------------
__global__ void k_posmean(const float* __restrict__ pos) {
    int blk = blockIdx.x;
    int t = threadIdx.x;
    __shared__ float s[64 * 3];
    s[t * 3 + 0] = pos[(blk * 64 + t) * 3 + 0];
    s[t * 3 + 1] = pos[(blk * 64 + t) * 3 + 1];
    s[t * 3 + 2] = pos[(blk * 64 + t) * 3 + 2];
    __syncthreads();
    if (t < 3) {
        float sum = 0.f;
        for (int i = 0; i < 64; i++) sum += s[i * 3 + t];
        g_scratch[OFF_PM + blk * 3 + t] = sum / 64.f;
    }
}

// ---------------- PE add + RMSNorm ----------------
__global__ void k_pe_norm(const float* __restrict__ x, const float* __restrict__ pos,
                          const float* __restrict__ peW, const float* __restrict__ peb,
                          const float* __restrict__ nsc) {
    int r = blockIdx.x;
    int t = threadIdx.x;
    int blk = r >> 6;
    float r0 = pos[r * 3 + 0] - g_scratch[OFF_PM + blk * 3 + 0];
    float r1 = pos[r * 3 + 1] - g_scratch[OFF_PM + blk * 3 + 1];
    float r2 = pos[r * 3 + 2] - g_scratch[OFF_PM + blk * 3 + 2];
    int c0 = t, c1 = t + 256;
    float v0 = x[(size_t)r * 512 + c0] + r0 * peW[c0] + r1 * peW[512 + c0] + r2 * peW[1024 + c0] + peb[c0];
    float v1 = x[(size_t)r * 512 + c1] + r0 * peW[c1] + r1 * peW[512 + c1] + r2 * peW[1024 + c1] + peb[c1];
    __shared__ float red[256];
    red[t] = v0 * v0 + v1 * v1;
    __syncthreads();
    for (int s = 128; s > 0; s >>= 1) {
        if (t < s) red[t] += red[t + s];
        __syncthreads();
    }
    float rms = rsqrtf(red[0] / 512.f + 1e-6f);
    g_scratch[OFF_INP + (size_t)r * 512 + c0] = v0 * rms * nsc[c0];
    g_scratch[OFF_INP + (size_t)r * 512 + c1] = v1 * rms * nsc[c1];
}

// ---------------- 128x128 tiled GEMM, double-buffered, optional dual-job + split-K ----
// grid: (N/128, M/128, npairs*nchunks). z -> comp = z/nchunks, chunk = z%nchunks.
// C (per comp) gets partials at chunk offset chunk*M*N. No bias/relu here.
__global__ void __launch_bounds__(256, 2)
k_gemm(const float* __restrict__ A0, const float* __restrict__ B0, float* __restrict__ C0,
       const float* __restrict__ A1, const float* __restrict__ B1, float* __restrict__ C1,
       int N, int K, int klen, int nchunks) {
    __shared__ float As[2][8][128];
    __shared__ float Bs[2][8][128];
    int z = blockIdx.z;
    int comp = z / nchunks, chunk = z - comp * nchunks;
    const float* A = comp ? A1 : A0;
    const float* B = comp ? B1 : B0;
    float* C = (comp ? C1 : C0) + (size_t)chunk * gridDim.y * 128 * N;
    int kstart = chunk * klen;
    int t = threadIdx.x;
    int bx = blockIdx.x, by = blockIdx.y;
    int arow = t >> 1, acolh = (t & 1) * 4;
    int brow = t >> 5, bcol = (t & 31) * 4;
    const float* Ag = A + (size_t)(by * 128 + arow) * K + kstart + acolh;
    const float* Bg = B + (size_t)(kstart + brow) * N + bx * 128 + bcol;
    int tx = t & 15, ty = t >> 4;
    float acc[8][8];
#pragma unroll
    for (int i = 0; i < 8; i++)
#pragma unroll
        for (int j = 0; j < 8; j++) acc[i][j] = 0.f;
    int tiles = klen / 8;
    float4 va = *(const float4*)Ag;
    float4 vb = *(const float4*)Bg;
    As[0][acolh + 0][arow] = va.x; As[0][acolh + 1][arow] = va.y;
    As[0][acolh + 2][arow] = va.z; As[0][acolh + 3][arow] = va.w;
    *(float4*)&Bs[0][brow][bcol] = vb;
    __syncthreads();
    for (int tk = 0; tk < tiles; tk++) {
        int cur = tk & 1;
        if (tk + 1 < tiles) {
            va = *(const float4*)(Ag + (tk + 1) * 8);
            vb = *(const float4*)(Bg + (size_t)(tk + 1) * 8 * N);
        }
#pragma unroll
        for (int kk = 0; kk < 8; kk++) {
            float a[8], b[8];
            *(float4*)&a[0] = *(float4*)&As[cur][kk][ty * 8];
            *(float4*)&a[4] = *(float4*)&As[cur][kk][ty * 8 + 4];
            *(float4*)&b[0] = *(float4*)&Bs[cur][kk][tx * 8];
            *(float4*)&b[4] = *(float4*)&Bs[cur][kk][tx * 8 + 4];
#pragma unroll
            for (int i = 0; i < 8; i++)
#pragma unroll
                for (int j = 0; j < 8; j++) acc[i][j] += a[i] * b[j];
        }
        if (tk + 1 < tiles) {
            int nxt = cur ^ 1;
            As[nxt][acolh + 0][arow] = va.x; As[nxt][acolh + 1][arow] = va.y;
            As[nxt][acolh + 2][arow] = va.z; As[nxt][acolh + 3][arow] = va.w;
            *(float4*)&Bs[nxt][brow][bcol] = vb;
        }
        __syncthreads();
    }
    int row0 = by * 128 + ty * 8;
    int col0 = bx * 128 + tx * 8;
#pragma unroll
    for (int i = 0; i < 8; i++) {
#pragma unroll
        for (int j = 0; j < 8; j += 4) {
            float4 v = make_float4(acc[i][j], acc[i][j + 1], acc[i][j + 2], acc[i][j + 3]);
            *(float4*)&C[(size_t)(row0 + i) * N + col0 + j] = v;
        }
    }
}

// ---------------- c1 split-K reduce + bias + relu ----------------
__global__ void k_c1red(const float* __restrict__ kcb1, const float* __restrict__ vcb1) {
    int u4 = blockIdx.x * 256 + threadIdx.x;   // 0..262143 (float4 units)
    int comp = u4 >> 17;
    int loc = u4 & 131071;                      // float4 idx within comp (128x4096/4)
    int col4 = loc & 1023;
    const float* P = g_scratch + OFF_PART + (size_t)comp * 2097152 + (size_t)loc * 4;
    float4 s0 = *(const float4*)(P);
    float4 s1 = *(const float4*)(P + 524288);
    float4 s2 = *(const float4*)(P + 1048576);
    float4 s3 = *(const float4*)(P + 1572864);
    const float* bias = comp ? vcb1 : kcb1;
    float4 b = *(const float4*)&bias[col4 * 4];
    float4 o;
    o.x = fmaxf(s0.x + s1.x + s2.x + s3.x + b.x, 0.f);
    o.y = fmaxf(s0.y + s1.y + s2.y + s3.y + b.y, 0.f);
    o.z = fmaxf(s0.z + s1.z + s2.z + s3.z + b.z, 0.f);
    o.w = fmaxf(s0.w + s1.w + s2.w + s3.w + b.w, 0.f);
    float* O = g_scratch + (comp ? OFF_VHID : OFF_KHID) + (size_t)loc * 4;
    *(float4*)O = o;
}

// ---------------- c2: 128x64x4096 per compressor, one row per block ----------------
__global__ void k_c2(const float* __restrict__ kcW2, const float* __restrict__ kcb2,
                     const float* __restrict__ vcW2, const float* __restrict__ vcb2) {
    int blk = blockIdx.x;              // 256 = comp*128 + row
    int comp = blk >> 7, row = blk & 127;
    const float* A = g_scratch + (comp ? OFF_VHID : OFF_KHID) + (size_t)row * 4096;
    const float* W = comp ? vcW2 : kcW2;
    const float* bias = comp ? vcb2 : kcb2;
    float* Cout = g_scratch + (comp ? OFF_CVRAW : OFF_CKRAW) + (size_t)row * 64;
    __shared__ float sa[4096];
    __shared__ float red[256];
    int t = threadIdx.x;
    for (int u = t * 4; u < 4096; u += 1024) *(float4*)&sa[u] = *(const float4*)&A[u];
    __syncthreads();
    int o = t & 63, sub = t >> 6;
    float acc = 0.f;
    const float* Wp = W + (size_t)(sub * 1024) * 64 + o;
    const float* ap = sa + sub * 1024;
#pragma unroll 4
    for (int kk = 0; kk < 1024; kk++) acc += ap[kk] * Wp[(size_t)kk * 64];
    red[t] = acc;
    __syncthreads();
    if (t < 64) Cout[t] = red[t] + red[64 + t] + red[128 + t] + red[192 + t] + bias[t];
}

// ---------------- split qkv + rope ----------------
__global__ void k_split_rope() {
    int r = blockIdx.x;
    int b = r >> 11;
    int i = r & 2047;
    int t = threadIdx.x;          // 384
    const float* qkv = g_scratch + OFF_QKV + (size_t)r * 768;
    if (t < 256) {
        int col = t * 2;
        int head = col >> 6, d = col & 63, j = d >> 1;
        float inv = powf(10000.f, -(float)j / 32.f);
        float cs, sn;
        sincosf((float)i * inv, &sn, &cs);
        float a = qkv[col], bb = qkv[col + 1];
        size_t base = (((size_t)(b * 8 + head) * 2048 + i) * 64 + d);
        g_scratch[OFF_Q + base] = a * cs - bb * sn;
        g_scratch[OFF_Q + base + 1] = bb * cs + a * sn;
    } else if (t < 320) {
        int ci = (t - 256) * 2;
        int g = ci >> 6, d = ci & 63, j = d >> 1;
        float inv = powf(10000.f, -(float)j / 32.f);
        float cs, sn;
        sincosf((float)i * inv, &sn, &cs);
        float a = qkv[512 + ci], bb = qkv[512 + ci + 1];
        size_t base = (((size_t)(b * 2 + g) * 2048 + i) * 64 + d);
        g_scratch[OFF_K + base] = a;
        g_scratch[OFF_K + base + 1] = bb;
        g_scratch[OFF_KR + base] = a * cs - bb * sn;
        g_scratch[OFF_KR + base + 1] = bb * cs + a * sn;
    } else {
        int ci = (t - 320) * 2;
        int g = ci >> 6, d = ci & 63;
        size_t base = (((size_t)(b * 2 + g) * 2048 + i) * 64 + d);
        g_scratch[OFF_V + base] = qkv[640 + ci];
        g_scratch[OFF_V + base + 1] = qkv[640 + ci + 1];
    }
}

// ---------------- build compressor input matrices ----------------
__global__ void k_buildmats(const float* __restrict__ k_pos, const float* __restrict__ v_pos) {
    int idx = blockIdx.x * blockDim.x + threadIdx.x;
    if (idx >= 128 * 4096) return;
    int row = idx >> 12, col = idx & 4095;
    int bg = row >> 5, wi = row & 31, g = bg & 1;
    int j = col >> 6, d = col & 63;
    size_t src = ((size_t)bg * 2048 + wi * 64 + j) * 64 + d;
    float pk = k_pos[(g * 64 + j) * 64 + d];
    float pv = v_pos[(g * 64 + j) * 64 + d];
    g_scratch[OFF_KBM + idx] = g_scratch[OFF_K + src] + pk;
    g_scratch[OFF_VBM + idx] = g_scratch[OFF_V + src] + pv;
}

// ---------------- pack ck/cv with mem token ----------------
__global__ void k_pack(const float* __restrict__ mem_k, const float* __restrict__ mem_v) {
    int idx = blockIdx.x * blockDim.x + threadIdx.x;
    if (idx >= 2 * 2 * 33 * 64) return;
    int d = idx & 63;
    int rest = idx >> 6;
    int j = rest % 33;
    int bg = rest / 33;
    int g = bg & 1;
    float kv, vv;
    if (j == 0) {
        kv = mem_k[g * 64 + d];
        vv = mem_v[g * 64 + d];
    } else {
        size_t s = ((size_t)bg * 32 + (j - 1)) * 64 + d;
        kv = g_scratch[OFF_CKRAW + s];
        vv = g_scratch[OFF_CVRAW + s];
    }
    g_scratch[OFF_CK + idx] = kv;
    g_scratch[OFF_CV + idx] = vv;
}

// ---------------- coarse attention + importance ----------------
__global__ void k_coarse() {
    int bi = blockIdx.x;
    int bg = bi >> 11, i = bi & 2047;
    int b = bg >> 1, g = bg & 1;
    int t = threadIdx.x;          // 128
    __shared__ float sck[33 * 64], scv[33 * 64], sq[4 * 64], sp[4 * 36];
    for (int u = t; u < 528; u += 128) {
        *(float4*)&sck[u * 4] = *(const float4*)&g_scratch[OFF_CK + (size_t)bg * 2112 + u * 4];
        *(float4*)&scv[u * 4] = *(const float4*)&g_scratch[OFF_CV + (size_t)bg * 2112 + u * 4];
    }
    for (int u = t; u < 256; u += 128) {
        int hq = u >> 6, d = u & 63;
        sq[u] = g_scratch[OFF_Q + (((size_t)(b * 8 + g * 4 + hq) * 2048 + i) * 64 + d)];
    }
    __syncthreads();
    for (int u = t; u < 132; u += 128) {
        int hq = u / 33, j = u % 33;
        float s = -1e30f;
        if (j == 0 || j * 64 <= i) {
            float acc = 0.f;
            const float4* qv = (const float4*)&sq[hq * 64];
            const float4* kv = (const float4*)&sck[j * 64];
#pragma unroll
            for (int d4 = 0; d4 < 16; d4++) {
                float4 a = qv[d4], bb = kv[d4];
                acc += a.x * bb.x + a.y * bb.y + a.z * bb.z + a.w * bb.w;
            }
            s = acc * 0.125f;
        }
        sp[hq * 36 + j] = s;
    }
    __syncthreads();
    if (t < 4) {
        float m = -1e30f;
        for (int j = 0; j < 33; j++) m = fmaxf(m, sp[t * 36 + j]);
        float sum = 0.f;
        for (int j = 0; j < 33; j++) {
            float e = __expf(sp[t * 36 + j] - m);
            sp[t * 36 + j] = e;
            sum += e;
        }
        float inv = 1.f / sum;
        for (int j = 0; j < 33; j++) sp[t * 36 + j] *= inv;
    }
    __syncthreads();
    if (t < 32) {
        g_scratch[OFF_IMP + ((size_t)bg * 2048 + i) * 32 + t] =
            0.25f * (sp[t + 1] + sp[36 + t + 1] + sp[72 + t + 1] + sp[108 + t + 1]);
    }
    for (int u = t; u < 256; u += 128) {
        int hq = u >> 6, d = u & 63;
        float acc = 0.f;
#pragma unroll
        for (int j4 = 0; j4 < 8; j4++) {
            float4 p = *(const float4*)&sp[hq * 36 + j4 * 4];
            acc += p.x * scv[(j4 * 4 + 0) * 64 + d] + p.y * scv[(j4 * 4 + 1) * 64 + d] +
                   p.z * scv[(j4 * 4 + 2) * 64 + d] + p.w * scv[(j4 * 4 + 3) * 64 + d];
        }
        acc += sp[hq * 36 + 32] * scv[32 * 64 + d];
        g_scratch[OFF_COUT + (((size_t)(b * 8 + g * 4 + hq) * 2048 + i) * 64 + d)] = acc;
    }
}

// ---------------- top-k (k=2, stable) ----------------
__global__ void k_topk() {
    int idx = blockIdx.x * blockDim.x + threadIdx.x;
    if (idx >= 8192) return;
    const float* imp = g_scratch + OFF_IMP + (size_t)idx * 32;
    int i1 = 0;
    float v1 = imp[0];
    for (int j = 1; j < 32; j++)
        if (imp[j] > v1) { v1 = imp[j]; i1 = j; }
    int i2 = -1;
    float v2 = -1e30f;
    for (int j = 0; j < 32; j++) {
        if (j == i1) continue;
        if (imp[j] > v2) { v2 = imp[j]; i2 = j; }
    }
    g_scratch[OFF_SELVAL + idx * 2 + 0] = v1;
    g_scratch[OFF_SELVAL + idx * 2 + 1] = v2;
    g_selidx[idx * 2 + 0] = i1;
    g_selidx[idx * 2 + 1] = i2;
}

// ---------------- fine gathered attention ----------------
#define FINE_SMEM ((192 * 64 * 2 + 256 + 768) * 4)
extern __shared__ float fsm[];
__global__ void k_fine() {
    float* sk = fsm;              // 192*64
    float* sv = fsm + 12288;      // 192*64
    float* sq = fsm + 24576;      // 256
    float* sp = fsm + 24832;      // 4*192
    int bi = blockIdx.x;
    int bg = bi >> 11, i = bi & 2047;
    int b = bg >> 1, g = bg & 1;
    int t = threadIdx.x;          // 256
    int own = i >> 6;
    __shared__ int blkid[3];
    __shared__ int okf[3];
    if (t < 2) {
        int si = g_selidx[bi * 2 + t];
        float sval = g_scratch[OFF_SELVAL + bi * 2 + t];
        blkid[t] = si;
        okf[t] = (sval > 0.f && si != own) ? 1 : 0;
    }
    if (t == 2) { blkid[2] = own; okf[2] = 1; }
    __syncthreads();
    size_t kbase = (size_t)bg * 2048 * 64;
    for (int u = t; u < 3072; u += 256) {          // float4 units
        int kk = u >> 4, d4 = u & 15;
        int kb = kk >> 6, j = kk & 63;
        size_t src = kbase + (size_t)(blkid[kb] * 64 + j) * 64 + d4 * 4;
        *(float4*)&sk[u * 4] = *(const float4*)&g_scratch[OFF_KR + src];
        *(float4*)&sv[u * 4] = *(const float4*)&g_scratch[OFF_V + src];
    }
    {
        int hq = t >> 6, d = t & 63;
        sq[t] = g_scratch[OFF_Q + (((size_t)(b * 8 + g * 4 + hq) * 2048 + i) * 64 + d)];
    }
    __syncthreads();
    int ilocal = i & 63;
    for (int u = t; u < 768; u += 256) {
        int hq = u / 192, kk = u % 192;
        int kb = kk >> 6, j = kk & 63;
        bool valid = (kb < 2) ? (okf[kb] != 0) : (j <= ilocal);
        float s = -1e30f;
        if (valid) {
            float acc = 0.f;
            const float4* qv = (const float4*)&sq[hq * 64];
            const float4* kv = (const float4*)&sk[kk * 64];
#pragma unroll
            for (int d4 = 0; d4 < 16; d4++) {
                float4 a = qv[d4], bb = kv[d4];
                acc += a.x * bb.x + a.y * bb.y + a.z * bb.z + a.w * bb.w;
            }
            s = acc * 0.125f;
        }
        sp[u] = s;
    }
    __syncthreads();
    int w = t >> 5, lane = t & 31;
    if (w < 4) {
        float m = -1e30f;
        for (int kk = lane; kk < 192; kk += 32) m = fmaxf(m, sp[w * 192 + kk]);
        for (int o = 16; o; o >>= 1) m = fmaxf(m, __shfl_xor_sync(~0u, m, o));
        float sum = 0.f;
        for (int kk = lane; kk < 192; kk += 32) {
            float e = __expf(sp[w * 192 + kk] - m);
            sp[w * 192 + kk] = e;
            sum += e;
        }
        for (int o = 16; o; o >>= 1) sum += __shfl_xor_sync(~0u, sum, o);
        float inv = 1.f / sum;
        for (int kk = lane; kk < 192; kk += 32) sp[w * 192 + kk] *= inv;
    }
    __syncthreads();
    {
        int hq = t >> 6, d = t & 63;
        float acc = 0.f;
#pragma unroll
        for (int kk = 0; kk < 192; kk += 4) {
            float4 p = *(const float4*)&sp[hq * 192 + kk];
            acc += p.x * sv[(kk + 0) * 64 + d] + p.y * sv[(kk + 1) * 64 + d] +
                   p.z * sv[(kk + 2) * 64 + d] + p.w * sv[(kk + 3) * 64 + d];
        }
        g_scratch[OFF_FOUT + (((size_t)(b * 8 + g * 4 + hq) * 2048 + i) * 64 + d)] = acc;
    }
}

// ---------------- sliding attention: register-tiled ----------------
// smem: sQt[d][q] 64x68 | sKt[d][kk] 64x260 (later V[kk][d] 256x64) | sS[kk][q] 256x68
#define SLIDE_SMEM ((4352 + 16640 + 17408) * 4)
extern __shared__ float ssm2[];
__global__ void k_slide() {
    float* sQt = ssm2;
    float* sKt = ssm2 + 4352;
    float* sS  = ssm2 + 4352 + 16640;
    int id = blockIdx.x;          // ((b*8+hh)*8 + tile)*4 + qc
    int qc = id & 3;
    int tile = (id >> 2) & 7;
    int hh = (id >> 5) & 7;
    int b = id >> 8;
    int g = hh >> 2;
    int t = threadIdx.x;          // 256
    size_t kbase = ((size_t)(b * 2 + g) * 2048 + (size_t)tile * 256) * 64;
    size_t qbase = (((size_t)(b * 8 + hh) * 2048) + tile * 256 + qc * 64) * 64;
    for (int u = t; u < 16384; u += 256) {
        int kk = u >> 6, d = u & 63;
        sKt[d * 260 + kk] = g_scratch[OFF_KR + kbase + u];
    }
    for (int u = t; u < 4096; u += 256) {
        int q = u >> 6, d = u & 63;
        sQt[d * 68 + q] = g_scratch[OFF_Q + qbase + u];
    }
    __syncthreads();
    // QK: acc[i=kk 8][j=q 8]
    {
        int q0 = (t & 7) * 8, kk0 = (t >> 3) * 8;
        float acc[8][8];
#pragma unroll
        for (int i = 0; i < 8; i++)
#pragma unroll
            for (int j = 0; j < 8; j++) acc[i][j] = 0.f;
        for (int d = 0; d < 64; d++) {
            float a[8], bb[8];
            *(float4*)&a[0] = *(float4*)&sQt[d * 68 + q0];
            *(float4*)&a[4] = *(float4*)&sQt[d * 68 + q0 + 4];
            *(float4*)&bb[0] = *(float4*)&sKt[d * 260 + kk0];
            *(float4*)&bb[4] = *(float4*)&sKt[d * 260 + kk0 + 4];
#pragma unroll
            for (int i = 0; i < 8; i++)
#pragma unroll
                for (int j = 0; j < 8; j++) acc[i][j] += bb[i] * a[j];
        }
#pragma unroll
        for (int i = 0; i < 8; i++)
#pragma unroll
            for (int j = 0; j < 8; j += 4) {
                float4 v = make_float4(acc[i][j] * 0.125f, acc[i][j + 1] * 0.125f,
                                       acc[i][j + 2] * 0.125f, acc[i][j + 3] * 0.125f);
                *(float4*)&sS[(kk0 + i) * 68 + q0 + j] = v;
            }
    }
    __syncthreads();
    // softmax per q column
    {
        int w = t >> 5, lane = t & 31;
#pragma unroll
        for (int qq = 0; qq < 8; qq++) {
            int q = w * 8 + qq;
            float vals[8];
#pragma unroll
            for (int j = 0; j < 8; j++) vals[j] = sS[(lane + j * 32) * 68 + q];
            float m = vals[0];
#pragma unroll
            for (int j = 1; j < 8; j++) m = fmaxf(m, vals[j]);
            for (int o = 16; o; o >>= 1) m = fmaxf(m, __shfl_xor_sync(~0u, m, o));
            float sum = 0.f;
#pragma unroll
            for (int j = 0; j < 8; j++) { vals[j] = __expf(vals[j] - m); sum += vals[j]; }
            for (int o = 16; o; o >>= 1) sum += __shfl_xor_sync(~0u, sum, o);
            float inv = 1.f / sum;
#pragma unroll
            for (int j = 0; j < 8; j++) sS[(lane + j * 32) * 68 + q] = vals[j] * inv;
        }
    }
    __syncthreads();
    // V into K region, layout [kk][d]
    for (int u = t; u < 16384; u += 256) sKt[u] = g_scratch[OFF_V + kbase + u];
    __syncthreads();
    // PV: out[q][d], 4x4 per thread
    {
        int pq = (t >> 4) * 4, pd = (t & 15) * 4;
        float o[4][4];
#pragma unroll
        for (int i = 0; i < 4; i++)
#pragma unroll
            for (int j = 0; j < 4; j++) o[i][j] = 0.f;
        for (int kk = 0; kk < 256; kk++) {
            float a[4], bb[4];
            *(float4*)&a[0] = *(float4*)&sS[kk * 68 + pq];
            *(float4*)&bb[0] = *(float4*)&sKt[kk * 64 + pd];
#pragma unroll
            for (int i = 0; i < 4; i++)
#pragma unroll
                for (int j = 0; j < 4; j++) o[i][j] += a[i] * bb[j];
        }
#pragma unroll
        for (int i = 0; i < 4; i++) {
            float4 v = make_float4(o[i][0], o[i][1], o[i][2], o[i][3]);
            *(float4*)&g_scratch[OFF_SOUT + qbase + (size_t)(pq + i) * 64 + pd] = v;
        }
    }
}

// ---------------- gates ----------------
__global__ void k_gates(const float* __restrict__ Wg, const float* __restrict__ bgv) {
    int r = blockIdx.x;
    int t = threadIdx.x;          // 128
    __shared__ float sx[512];
    for (int u = t; u < 512; u += 128) sx[u] = g_scratch[OFF_INP + (size_t)r * 512 + u];
    __syncthreads();
    int w = t >> 5, lane = t & 31;
    for (int o = w; o < 24; o += 4) {
        float acc = 0.f;
        for (int kk = lane; kk < 512; kk += 32) acc += sx[kk] * Wg[(size_t)kk * 24 + o];
        for (int off = 16; off; off >>= 1) acc += __shfl_xor_sync(~0u, acc, off);
        if (lane == 0)
            g_scratch[OFF_GATES + (size_t)r * 24 + o] = 1.f / (1.f + __expf(-(acc + bgv[o])));
    }
}

// ---------------- combine ----------------
__global__ void k_combine() {
    int idx = blockIdx.x * blockDim.x + threadIdx.x;
    if (idx >= 4096 * 512) return;
    int d = idx & 63;
    int hh = (idx >> 6) & 7;
    int ri = idx >> 9;
    int b = ri >> 11, i = ri & 2047;
    size_t hidx = (((size_t)(b * 8 + hh) * 2048 + i) * 64 + d);
    const float* gg = g_scratch + OFF_GATES + (size_t)ri * 24 + hh * 3;
    g_scratch[OFF_COMB + idx] = gg[0] * g_scratch[OFF_COUT + hidx] +
                                gg[1] * g_scratch[OFF_FOUT + hidx] +
                                gg[2] * g_scratch[OFF_SOUT + hidx];
}

// ---------------- host ----------------
extern "C" void kernel_launch(void* const* d_in, const int* in_sizes, int n_in,
                              void* d_out, int out_size) {
    const float* x     = (const float*)d_in[0];
    const float* pos   = (const float*)d_in[1];
    const float* pe_W  = (const float*)d_in[2];
    const float* pe_b  = (const float*)d_in[3];
    const float* nsc   = (const float*)d_in[4];
    const float* Wqkv  = (const float*)d_in[5];
    const float* k_pos = (const float*)d_in[6];
    const float* v_pos = (const float*)d_in[7];
    const float* kcW1  = (const float*)d_in[8];
    const float* kcb1  = (const float*)d_in[9];
    const float* kcW2  = (const float*)d_in[10];
    const float* kcb2  = (const float*)d_in[11];
    const float* vcW1  = (const float*)d_in[12];
    const float* vcb1  = (const float*)d_in[13];
    const float* vcW2  = (const float*)d_in[14];
    const float* vcb2  = (const float*)d_in[15];
    const float* mem_k = (const float*)d_in[16];
    const float* mem_v = (const float*)d_in[17];
    const float* Wg    = (const float*)d_in[18];
    const float* bgv   = (const float*)d_in[19];
    const float* Wo    = (const float*)d_in[20];
    float* out = (float*)d_out;

    float* S = nullptr;
    cudaGetSymbolAddress((void**)&S, g_scratch);

    cudaFuncSetAttribute(k_fine, cudaFuncAttributeMaxDynamicSharedMemorySize, FINE_SMEM);
    cudaFuncSetAttribute(k_slide, cudaFuncAttributeMaxDynamicSharedMemorySize, SLIDE_SMEM);

    k_posmean<<<64, 64>>>(pos);
    k_pe_norm<<<4096, 256>>>(x, pos, pe_W, pe_b, nsc);

    // qkv = inp @ Wqkv : M=4096 N=768 K=512
    k_gemm<<<dim3(6, 32, 1), 256>>>(S + OFF_INP, Wqkv, S + OFF_QKV,
                                    S + OFF_INP, Wqkv, S + OFF_QKV, 768, 512, 512, 1);
    k_split_rope<<<4096, 384>>>();
    k_buildmats<<<(128 * 4096 + 255) / 256, 256>>>(k_pos, v_pos);

    // fused kc1+vc1, split-K 4: M=128 N=4096 K=4096
    k_gemm<<<dim3(32, 1, 8), 256>>>(S + OFF_KBM, kcW1, S + OFF_PART,
                                    S + OFF_VBM, vcW1, S + OFF_PART + 2097152,
                                    4096, 4096, 1024, 4);
    k_c1red<<<1024, 256>>>(kcb1, vcb1);
    k_c2<<<256, 256>>>(kcW2, kcb2, vcW2, vcb2);
    k_pack<<<(8448 + 255) / 256, 256>>>(mem_k, mem_v);

    k_coarse<<<8192, 128>>>();
    k_topk<<<32, 256>>>();
    k_fine<<<8192, 256, FINE_SMEM>>>();
    k_slide<<<512, 256, SLIDE_SMEM>>>();
    k_gates<<<4096, 128>>>(Wg, bgv);
    k_combine<<<(4096 * 512 + 255) / 256, 256>>>();

    // out = comb @ Wo : M=4096 N=512 K=512
    k_gemm<<<dim3(4, 32, 1), 256>>>(S + OFF_COMB, Wo, out,
                                    S + OFF_COMB, Wo, out, 512, 512, 512, 1);
}

// round 5
// speedup vs baseline: 2.1954x; 1.1175x over previous
#include <cuda_runtime.h>
#include <cuda_bf16.h>
#include <math.h>
#include <stdint.h>

// ---------------- scratch layout (floats) ----------------
#define OFF_INP     0ul
#define OFF_QKV     2097152ul
#define OFF_Q       5242880ul
#define OFF_K       7340032ul
#define OFF_KR      7864320ul
#define OFF_V       8388608ul
#define OFF_KBM     8912896ul
#define OFF_VBM     9437184ul
#define OFF_KHID    9961472ul
#define OFF_VHID   10485760ul
#define OFF_CKRAW  11010048ul
#define OFF_CVRAW  11018240ul
#define OFF_CK     11026432ul
#define OFF_CV     11034880ul
#define OFF_COUT   11043328ul
#define OFF_FOUT   13140480ul
#define OFF_SOUT   15237632ul
#define OFF_IMP    17334784ul
#define OFF_SELVAL 17596928ul
#define OFF_GATES  17613312ul
#define OFF_COMB   17711616ul
#define OFF_PM     19808768ul
#define OFF_PART   19808960ul   /* 2 comps x 4 chunks x 128 x 4096 */
#define SCRATCH_SZ 24003264ul

__device__ float g_scratch[SCRATCH_SZ];
__device__ int   g_selidx[2 * 2 * 2048 * 2];

// ================= warp-MMA helpers (sm_80+, valid on base sm_100) ============
__device__ __forceinline__ uint32_t smem_u32(const void* p) {
    uint32_t a;
    asm("{ .reg .u64 tmp; cvta.to.shared.u64 tmp, %1; cvt.u32.u64 %0, tmp; }"
        : "=r"(a) : "l"(p));
    return a;
}
__device__ __forceinline__ void ldsm_x4(uint32_t& r0, uint32_t& r1, uint32_t& r2, uint32_t& r3,
                                        uint32_t addr) {
    asm volatile("ldmatrix.sync.aligned.m8n8.x4.shared.b16 {%0,%1,%2,%3}, [%4];"
                 : "=r"(r0), "=r"(r1), "=r"(r2), "=r"(r3) : "r"(addr));
}
__device__ __forceinline__ void ldsm_x4t(uint32_t& r0, uint32_t& r1, uint32_t& r2, uint32_t& r3,
                                         uint32_t addr) {
    asm volatile("ldmatrix.sync.aligned.m8n8.x4.trans.shared.b16 {%0,%1,%2,%3}, [%4];"
                 : "=r"(r0), "=r"(r1), "=r"(r2), "=r"(r3) : "r"(addr));
}
__device__ __forceinline__ void mma16816(float* c, uint32_t a0, uint32_t a1, uint32_t a2,
                                         uint32_t a3, uint32_t b0, uint32_t b1) {
    asm volatile("mma.sync.aligned.m16n8k16.row.col.f32.bf16.bf16.f32 "
                 "{%0,%1,%2,%3}, {%4,%5,%6,%7}, {%8,%9}, {%0,%1,%2,%3};"
                 : "+f"(c[0]), "+f"(c[1]), "+f"(c[2]), "+f"(c[3])
                 : "r"(a0), "r"(a1), "r"(a2), "r"(a3), "r"(b0), "r"(b1));
}
__device__ __forceinline__ void bf_split_pack(float x0, float x1, uint32_t& hp, uint32_t& lp) {
    __nv_bfloat16 h0 = __float2bfloat16(x0);
    __nv_bfloat16 h1 = __float2bfloat16(x1);
    __nv_bfloat16 l0 = __float2bfloat16(x0 - __bfloat162float(h0));
    __nv_bfloat16 l1 = __float2bfloat16(x1 - __bfloat162float(h1));
    hp = ((uint32_t)__bfloat16_as_ushort(h1) << 16) | __bfloat16_as_ushort(h0);
    lp = ((uint32_t)__bfloat16_as_ushort(l1) << 16) | __bfloat16_as_ushort(l0);
}

// ======== bf16x3 MMA GEMM: C[M x N] = A[M x K] @ B[K x N], dual-job + split-K ====
// grid (N/128, M/128, npairs*nchunks). z -> comp=z/nchunks, chunk=z%nchunks.
// Partials land at chunk * gridDim.y*128*N (raw, no bias/relu).
#define APAD 40
#define BPAD 136
__global__ void __launch_bounds__(256, 1)
k_mgemm(const float* __restrict__ A0, const float* __restrict__ B0, float* __restrict__ C0,
        const float* __restrict__ A1, const float* __restrict__ B1, float* __restrict__ C1,
        int N, int K, int klen, int nchunks) {
    __shared__ __align__(16) uint16_t sAhi[128 * APAD];
    __shared__ __align__(16) uint16_t sAlo[128 * APAD];
    __shared__ __align__(16) uint16_t sBhi[32 * BPAD];
    __shared__ __align__(16) uint16_t sBlo[32 * BPAD];
    int z = blockIdx.z;
    int comp = z / nchunks, chunk = z - comp * nchunks;
    const float* A = comp ? A1 : A0;
    const float* B = comp ? B1 : B0;
    float* C = (comp ? C1 : C0) + (size_t)chunk * gridDim.y * 128 * N;
    int kstart = chunk * klen;
    int t = threadIdx.x, wid = t >> 5, lane = t & 31;
    int bx = blockIdx.x, by = blockIdx.y;
    int warp_m = wid >> 2, warp_n = wid & 3;   // 2 x 4

    float acc[4][4][4];
#pragma unroll
    for (int mt = 0; mt < 4; mt++)
#pragma unroll
        for (int nt = 0; nt < 4; nt++)
#pragma unroll
            for (int e = 0; e < 4; e++) acc[mt][nt][e] = 0.f;

    // ldmatrix source addresses (bf16-unit offsets)
    uint32_t a_hi_base = smem_u32(sAhi), a_lo_base = smem_u32(sAlo);
    uint32_t b_hi_base = smem_u32(sBhi), b_lo_base = smem_u32(sBlo);
    int a_row = (lane & 15), a_kc8 = 8 * (lane >> 4);
    int b_krow = (lane & 15), b_n8 = 8 * (lane >> 4);

    int nchunk32 = klen / 32;
    const float* Ab = A + (size_t)(by * 128) * K + kstart;
    const float* Bb = B + (size_t)kstart * N + bx * 128;

    for (int c = 0; c < nchunk32; c++) {
        // stage A chunk (128 x 32) as hi/lo
#pragma unroll
        for (int p = 0; p < 8; p++) {
            int u = t + p * 256;            // 2048 b32 units
            int row = u >> 4, kp = u & 15;
            float2 v = *(const float2*)&Ab[(size_t)row * K + c * 32 + kp * 2];
            uint32_t hp, lp;
            bf_split_pack(v.x, v.y, hp, lp);
            *(uint32_t*)&sAhi[row * APAD + kp * 2] = hp;
            *(uint32_t*)&sAlo[row * APAD + kp * 2] = lp;
        }
        // stage B chunk (32 x 128) as hi/lo
#pragma unroll
        for (int p = 0; p < 8; p++) {
            int u = t + p * 256;
            int kr = u >> 6, np = u & 63;
            float2 v = *(const float2*)&Bb[(size_t)(c * 32 + kr) * N + np * 2];
            uint32_t hp, lp;
            bf_split_pack(v.x, v.y, hp, lp);
            *(uint32_t*)&sBhi[kr * BPAD + np * 2] = hp;
            *(uint32_t*)&sBlo[kr * BPAD + np * 2] = lp;
        }
        __syncthreads();
#pragma unroll
        for (int ks = 0; ks < 2; ks++) {
            uint32_t ahi[4][4], alo[4][4], bhi[4][2], blo[4][2];
#pragma unroll
            for (int mt = 0; mt < 4; mt++) {
                int off = (warp_m * 64 + mt * 16 + a_row) * APAD + ks * 16 + a_kc8;
                ldsm_x4(ahi[mt][0], ahi[mt][1], ahi[mt][2], ahi[mt][3], a_hi_base + off * 2);
                ldsm_x4(alo[mt][0], alo[mt][1], alo[mt][2], alo[mt][3], a_lo_base + off * 2);
            }
#pragma unroll
            for (int nt2 = 0; nt2 < 2; nt2++) {
                int off = (ks * 16 + b_krow) * BPAD + warp_n * 32 + nt2 * 16 + b_n8;
                ldsm_x4t(bhi[nt2 * 2][0], bhi[nt2 * 2][1], bhi[nt2 * 2 + 1][0],
                         bhi[nt2 * 2 + 1][1], b_hi_base + off * 2);
                ldsm_x4t(blo[nt2 * 2][0], blo[nt2 * 2][1], blo[nt2 * 2 + 1][0],
                         blo[nt2 * 2 + 1][1], b_lo_base + off * 2);
            }
#pragma unroll
            for (int mt = 0; mt < 4; mt++)
#pragma unroll
                for (int nt = 0; nt < 4; nt++) {
                    mma16816(acc[mt][nt], ahi[mt][0], ahi[mt][1], ahi[mt][2], ahi[mt][3],
                             bhi[nt][0], bhi[nt][1]);
                    mma16816(acc[mt][nt], ahi[mt][0], ahi[mt][1], ahi[mt][2], ahi[mt][3],
                             blo[nt][0], blo[nt][1]);
                    mma16816(acc[mt][nt], alo[mt][0], alo[mt][1], alo[mt][2], alo[mt][3],
                             bhi[nt][0], bhi[nt][1]);
                }
        }
        __syncthreads();
    }
    // epilogue: direct float2 stores
    int g = lane >> 2, tid4 = lane & 3;
#pragma unroll
    for (int mt = 0; mt < 4; mt++) {
        int row0 = by * 128 + warp_m * 64 + mt * 16 + g;
#pragma unroll
        for (int nt = 0; nt < 4; nt++) {
            int col = bx * 128 + warp_n * 32 + nt * 8 + tid4 * 2;
            *(float2*)&C[(size_t)row0 * N + col] = make_float2(acc[mt][nt][0], acc[mt][nt][1]);
            *(float2*)&C[(size_t)(row0 + 8) * N + col] = make_float2(acc[mt][nt][2], acc[mt][nt][3]);
        }
    }
}

// ---------------- c1 split-K reduce + bias + relu ----------------
__global__ void k_c1red(const float* __restrict__ kcb1, const float* __restrict__ vcb1) {
    int u4 = blockIdx.x * 256 + threadIdx.x;   // 0..262143 (float4 units)
    int comp = u4 >> 17;
    int loc = u4 & 131071;                      // float4 idx within comp
    int col4 = loc & 1023;
    const float* P = g_scratch + OFF_PART + (size_t)comp * 2097152 + (size_t)loc * 4;
    float4 s0 = *(const float4*)(P);
    float4 s1 = *(const float4*)(P + 524288);
    float4 s2 = *(const float4*)(P + 1048576);
    float4 s3 = *(const float4*)(P + 1572864);
    const float* bias = comp ? vcb1 : kcb1;
    float4 b = *(const float4*)&bias[col4 * 4];
    float4 o;
    o.x = fmaxf(s0.x + s1.x + s2.x + s3.x + b.x, 0.f);
    o.y = fmaxf(s0.y + s1.y + s2.y + s3.y + b.y, 0.f);
    o.z = fmaxf(s0.z + s1.z + s2.z + s3.z + b.z, 0.f);
    o.w = fmaxf(s0.w + s1.w + s2.w + s3.w + b.w, 0.f);
    float* O = g_scratch + (comp ? OFF_VHID : OFF_KHID) + (size_t)loc * 4;
    *(float4*)O = o;
}

// ---------------- pos block means ----------------
__global__ void k_posmean(const float* __restrict__ pos) {
    int blk = blockIdx.x;
    int t = threadIdx.x;
    __shared__ float s[64 * 3];
    s[t * 3 + 0] = pos[(blk * 64 + t) * 3 + 0];
    s[t * 3 + 1] = pos[(blk * 64 + t) * 3 + 1];
    s[t * 3 + 2] = pos[(blk * 64 + t) * 3 + 2];
    __syncthreads();
    if (t < 3) {
        float sum = 0.f;
        for (int i = 0; i < 64; i++) sum += s[i * 3 + t];
        g_scratch[OFF_PM + blk * 3 + t] = sum / 64.f;
    }
}

// ---------------- PE add + RMSNorm ----------------
__global__ void k_pe_norm(const float* __restrict__ x, const float* __restrict__ pos,
                          const float* __restrict__ peW, const float* __restrict__ peb,
                          const float* __restrict__ nsc) {
    int r = blockIdx.x;
    int t = threadIdx.x;
    int blk = r >> 6;
    float r0 = pos[r * 3 + 0] - g_scratch[OFF_PM + blk * 3 + 0];
    float r1 = pos[r * 3 + 1] - g_scratch[OFF_PM + blk * 3 + 1];
    float r2 = pos[r * 3 + 2] - g_scratch[OFF_PM + blk * 3 + 2];
    int c0 = t, c1 = t + 256;
    float v0 = x[(size_t)r * 512 + c0] + r0 * peW[c0] + r1 * peW[512 + c0] + r2 * peW[1024 + c0] + peb[c0];
    float v1 = x[(size_t)r * 512 + c1] + r0 * peW[c1] + r1 * peW[512 + c1] + r2 * peW[1024 + c1] + peb[c1];
    __shared__ float red[256];
    red[t] = v0 * v0 + v1 * v1;
    __syncthreads();
    for (int s = 128; s > 0; s >>= 1) {
        if (t < s) red[t] += red[t + s];
        __syncthreads();
    }
    float rms = rsqrtf(red[0] / 512.f + 1e-6f);
    g_scratch[OFF_INP + (size_t)r * 512 + c0] = v0 * rms * nsc[c0];
    g_scratch[OFF_INP + (size_t)r * 512 + c1] = v1 * rms * nsc[c1];
}

// ---------------- c2: 128x64x4096 per compressor ----------------
__global__ void k_c2(const float* __restrict__ kcW2, const float* __restrict__ kcb2,
                     const float* __restrict__ vcW2, const float* __restrict__ vcb2) {
    int blk = blockIdx.x;              // 256 = comp*128 + row
    int comp = blk >> 7, row = blk & 127;
    const float* A = g_scratch + (comp ? OFF_VHID : OFF_KHID) + (size_t)row * 4096;
    const float* W = comp ? vcW2 : kcW2;
    const float* bias = comp ? vcb2 : kcb2;
    float* Cout = g_scratch + (comp ? OFF_CVRAW : OFF_CKRAW) + (size_t)row * 64;
    __shared__ float sa[4096];
    __shared__ float red[256];
    int t = threadIdx.x;
    for (int u = t * 4; u < 4096; u += 1024) *(float4*)&sa[u] = *(const float4*)&A[u];
    __syncthreads();
    int o = t & 63, sub = t >> 6;
    float acc = 0.f;
    const float* Wp = W + (size_t)(sub * 1024) * 64 + o;
    const float* ap = sa + sub * 1024;
#pragma unroll 4
    for (int kk = 0; kk < 1024; kk++) acc += ap[kk] * Wp[(size_t)kk * 64];
    red[t] = acc;
    __syncthreads();
    if (t < 64) Cout[t] = red[t] + red[64 + t] + red[128 + t] + red[192 + t] + bias[t];
}

// ---------------- split qkv + rope ----------------
__global__ void k_split_rope() {
    int r = blockIdx.x;
    int b = r >> 11;
    int i = r & 2047;
    int t = threadIdx.x;          // 384
    const float* qkv = g_scratch + OFF_QKV + (size_t)r * 768;
    if (t < 256) {
        int col = t * 2;
        int head = col >> 6, d = col & 63, j = d >> 1;
        float inv = powf(10000.f, -(float)j / 32.f);
        float cs, sn;
        sincosf((float)i * inv, &sn, &cs);
        float a = qkv[col], bb = qkv[col + 1];
        size_t base = (((size_t)(b * 8 + head) * 2048 + i) * 64 + d);
        g_scratch[OFF_Q + base] = a * cs - bb * sn;
        g_scratch[OFF_Q + base + 1] = bb * cs + a * sn;
    } else if (t < 320) {
        int ci = (t - 256) * 2;
        int g = ci >> 6, d = ci & 63, j = d >> 1;
        float inv = powf(10000.f, -(float)j / 32.f);
        float cs, sn;
        sincosf((float)i * inv, &sn, &cs);
        float a = qkv[512 + ci], bb = qkv[512 + ci + 1];
        size_t base = (((size_t)(b * 2 + g) * 2048 + i) * 64 + d);
        g_scratch[OFF_K + base] = a;
        g_scratch[OFF_K + base + 1] = bb;
        g_scratch[OFF_KR + base] = a * cs - bb * sn;
        g_scratch[OFF_KR + base + 1] = bb * cs + a * sn;
    } else {
        int ci = (t - 320) * 2;
        int g = ci >> 6, d = ci & 63;
        size_t base = (((size_t)(b * 2 + g) * 2048 + i) * 64 + d);
        g_scratch[OFF_V + base] = qkv[640 + ci];
        g_scratch[OFF_V + base + 1] = qkv[640 + ci + 1];
    }
}

// ---------------- build compressor input matrices ----------------
__global__ void k_buildmats(const float* __restrict__ k_pos, const float* __restrict__ v_pos) {
    int idx = blockIdx.x * blockDim.x + threadIdx.x;
    if (idx >= 128 * 4096) return;
    int row = idx >> 12, col = idx & 4095;
    int bg = row >> 5, wi = row & 31, g = bg & 1;
    int j = col >> 6, d = col & 63;
    size_t src = ((size_t)bg * 2048 + wi * 64 + j) * 64 + d;
    float pk = k_pos[(g * 64 + j) * 64 + d];
    float pv = v_pos[(g * 64 + j) * 64 + d];
    g_scratch[OFF_KBM + idx] = g_scratch[OFF_K + src] + pk;
    g_scratch[OFF_VBM + idx] = g_scratch[OFF_V + src] + pv;
}

// ---------------- pack ck/cv with mem token ----------------
__global__ void k_pack(const float* __restrict__ mem_k, const float* __restrict__ mem_v) {
    int idx = blockIdx.x * blockDim.x + threadIdx.x;
    if (idx >= 2 * 2 * 33 * 64) return;
    int d = idx & 63;
    int rest = idx >> 6;
    int j = rest % 33;
    int bg = rest / 33;
    int g = bg & 1;
    float kv, vv;
    if (j == 0) {
        kv = mem_k[g * 64 + d];
        vv = mem_v[g * 64 + d];
    } else {
        size_t s = ((size_t)bg * 32 + (j - 1)) * 64 + d;
        kv = g_scratch[OFF_CKRAW + s];
        vv = g_scratch[OFF_CVRAW + s];
    }
    g_scratch[OFF_CK + idx] = kv;
    g_scratch[OFF_CV + idx] = vv;
}

// ---------------- coarse attention + importance ----------------
__global__ void k_coarse() {
    int bi = blockIdx.x;
    int bg = bi >> 11, i = bi & 2047;
    int b = bg >> 1, g = bg & 1;
    int t = threadIdx.x;          // 128
    __shared__ float sck[33 * 64], scv[33 * 64], sq[4 * 64], sp[4 * 36];
    for (int u = t; u < 528; u += 128) {
        *(float4*)&sck[u * 4] = *(const float4*)&g_scratch[OFF_CK + (size_t)bg * 2112 + u * 4];
        *(float4*)&scv[u * 4] = *(const float4*)&g_scratch[OFF_CV + (size_t)bg * 2112 + u * 4];
    }
    for (int u = t; u < 256; u += 128) {
        int hq = u >> 6, d = u & 63;
        sq[u] = g_scratch[OFF_Q + (((size_t)(b * 8 + g * 4 + hq) * 2048 + i) * 64 + d)];
    }
    __syncthreads();
    for (int u = t; u < 132; u += 128) {
        int hq = u / 33, j = u % 33;
        float s = -1e30f;
        if (j == 0 || j * 64 <= i) {
            float acc = 0.f;
            const float4* qv = (const float4*)&sq[hq * 64];
            const float4* kv = (const float4*)&sck[j * 64];
#pragma unroll
            for (int d4 = 0; d4 < 16; d4++) {
                float4 a = qv[d4], bb = kv[d4];
                acc += a.x * bb.x + a.y * bb.y + a.z * bb.z + a.w * bb.w;
            }
            s = acc * 0.125f;
        }
        sp[hq * 36 + j] = s;
    }
    __syncthreads();
    if (t < 4) {
        float m = -1e30f;
        for (int j = 0; j < 33; j++) m = fmaxf(m, sp[t * 36 + j]);
        float sum = 0.f;
        for (int j = 0; j < 33; j++) {
            float e = __expf(sp[t * 36 + j] - m);
            sp[t * 36 + j] = e;
            sum += e;
        }
        float inv = 1.f / sum;
        for (int j = 0; j < 33; j++) sp[t * 36 + j] *= inv;
    }
    __syncthreads();
    if (t < 32) {
        g_scratch[OFF_IMP + ((size_t)bg * 2048 + i) * 32 + t] =
            0.25f * (sp[t + 1] + sp[36 + t + 1] + sp[72 + t + 1] + sp[108 + t + 1]);
    }
    for (int u = t; u < 256; u += 128) {
        int hq = u >> 6, d = u & 63;
        float acc = 0.f;
#pragma unroll
        for (int j4 = 0; j4 < 8; j4++) {
            float4 p = *(const float4*)&sp[hq * 36 + j4 * 4];
            acc += p.x * scv[(j4 * 4 + 0) * 64 + d] + p.y * scv[(j4 * 4 + 1) * 64 + d] +
                   p.z * scv[(j4 * 4 + 2) * 64 + d] + p.w * scv[(j4 * 4 + 3) * 64 + d];
        }
        acc += sp[hq * 36 + 32] * scv[32 * 64 + d];
        g_scratch[OFF_COUT + (((size_t)(b * 8 + g * 4 + hq) * 2048 + i) * 64 + d)] = acc;
    }
}

// ---------------- top-k (k=2, stable) ----------------
__global__ void k_topk() {
    int idx = blockIdx.x * blockDim.x + threadIdx.x;
    if (idx >= 8192) return;
    const float* imp = g_scratch + OFF_IMP + (size_t)idx * 32;
    int i1 = 0;
    float v1 = imp[0];
    for (int j = 1; j < 32; j++)
        if (imp[j] > v1) { v1 = imp[j]; i1 = j; }
    int i2 = -1;
    float v2 = -1e30f;
    for (int j = 0; j < 32; j++) {
        if (j == i1) continue;
        if (imp[j] > v2) { v2 = imp[j]; i2 = j; }
    }
    g_scratch[OFF_SELVAL + idx * 2 + 0] = v1;
    g_scratch[OFF_SELVAL + idx * 2 + 1] = v2;
    g_selidx[idx * 2 + 0] = i1;
    g_selidx[idx * 2 + 1] = i2;
}

// ---------------- fine gathered attention ----------------
#define FINE_SMEM ((192 * 64 * 2 + 256 + 768) * 4)
extern __shared__ float fsm[];
__global__ void k_fine() {
    float* sk = fsm;              // 192*64
    float* sv = fsm + 12288;      // 192*64
    float* sq = fsm + 24576;      // 256
    float* sp = fsm + 24832;      // 4*192
    int bi = blockIdx.x;
    int bg = bi >> 11, i = bi & 2047;
    int b = bg >> 1, g = bg & 1;
    int t = threadIdx.x;          // 256
    int own = i >> 6;
    __shared__ int blkid[3];
    __shared__ int okf[3];
    if (t < 2) {
        int si = g_selidx[bi * 2 + t];
        float sval = g_scratch[OFF_SELVAL + bi * 2 + t];
        blkid[t] = si;
        okf[t] = (sval > 0.f && si != own) ? 1 : 0;
    }
    if (t == 2) { blkid[2] = own; okf[2] = 1; }
    __syncthreads();
    size_t kbase = (size_t)bg * 2048 * 64;
    for (int u = t; u < 3072; u += 256) {          // float4 units
        int kk = u >> 4, d4 = u & 15;
        int kb = kk >> 6, j = kk & 63;
        size_t src = kbase + (size_t)(blkid[kb] * 64 + j) * 64 + d4 * 4;
        *(float4*)&sk[u * 4] = *(const float4*)&g_scratch[OFF_KR + src];
        *(float4*)&sv[u * 4] = *(const float4*)&g_scratch[OFF_V + src];
    }
    {
        int hq = t >> 6, d = t & 63;
        sq[t] = g_scratch[OFF_Q + (((size_t)(b * 8 + g * 4 + hq) * 2048 + i) * 64 + d)];
    }
    __syncthreads();
    int ilocal = i & 63;
    for (int u = t; u < 768; u += 256) {
        int hq = u / 192, kk = u % 192;
        int kb = kk >> 6, j = kk & 63;
        bool valid = (kb < 2) ? (okf[kb] != 0) : (j <= ilocal);
        float s = -1e30f;
        if (valid) {
            float acc = 0.f;
            const float4* qv = (const float4*)&sq[hq * 64];
            const float4* kv = (const float4*)&sk[kk * 64];
#pragma unroll
            for (int d4 = 0; d4 < 16; d4++) {
                float4 a = qv[d4], bb = kv[d4];
                acc += a.x * bb.x + a.y * bb.y + a.z * bb.z + a.w * bb.w;
            }
            s = acc * 0.125f;
        }
        sp[u] = s;
    }
    __syncthreads();
    int w = t >> 5, lane = t & 31;
    if (w < 4) {
        float m = -1e30f;
        for (int kk = lane; kk < 192; kk += 32) m = fmaxf(m, sp[w * 192 + kk]);
        for (int o = 16; o; o >>= 1) m = fmaxf(m, __shfl_xor_sync(~0u, m, o));
        float sum = 0.f;
        for (int kk = lane; kk < 192; kk += 32) {
            float e = __expf(sp[w * 192 + kk] - m);
            sp[w * 192 + kk] = e;
            sum += e;
        }
        for (int o = 16; o; o >>= 1) sum += __shfl_xor_sync(~0u, sum, o);
        float inv = 1.f / sum;
        for (int kk = lane; kk < 192; kk += 32) sp[w * 192 + kk] *= inv;
    }
    __syncthreads();
    {
        int hq = t >> 6, d = t & 63;
        float acc = 0.f;
#pragma unroll
        for (int kk = 0; kk < 192; kk += 4) {
            float4 p = *(const float4*)&sp[hq * 192 + kk];
            acc += p.x * sv[(kk + 0) * 64 + d] + p.y * sv[(kk + 1) * 64 + d] +
                   p.z * sv[(kk + 2) * 64 + d] + p.w * sv[(kk + 3) * 64 + d];
        }
        g_scratch[OFF_FOUT + (((size_t)(b * 8 + g * 4 + hq) * 2048 + i) * 64 + d)] = acc;
    }
}

// ---------------- sliding attention: register-tiled ----------------
#define SLIDE_SMEM ((4352 + 16640 + 17408) * 4)
extern __shared__ float ssm2[];
__global__ void k_slide() {
    float* sQt = ssm2;
    float* sKt = ssm2 + 4352;
    float* sS  = ssm2 + 4352 + 16640;
    int id = blockIdx.x;          // ((b*8+hh)*8 + tile)*4 + qc
    int qc = id & 3;
    int tile = (id >> 2) & 7;
    int hh = (id >> 5) & 7;
    int b = id >> 8;
    int g = hh >> 2;
    int t = threadIdx.x;          // 256
    size_t kbase = ((size_t)(b * 2 + g) * 2048 + (size_t)tile * 256) * 64;
    size_t qbase = (((size_t)(b * 8 + hh) * 2048) + tile * 256 + qc * 64) * 64;
    for (int u = t; u < 16384; u += 256) {
        int kk = u >> 6, d = u & 63;
        sKt[d * 260 + kk] = g_scratch[OFF_KR + kbase + u];
    }
    for (int u = t; u < 4096; u += 256) {
        int q = u >> 6, d = u & 63;
        sQt[d * 68 + q] = g_scratch[OFF_Q + qbase + u];
    }
    __syncthreads();
    {
        int q0 = (t & 7) * 8, kk0 = (t >> 3) * 8;
        float acc[8][8];
#pragma unroll
        for (int i = 0; i < 8; i++)
#pragma unroll
            for (int j = 0; j < 8; j++) acc[i][j] = 0.f;
        for (int d = 0; d < 64; d++) {
            float a[8], bb[8];
            *(float4*)&a[0] = *(float4*)&sQt[d * 68 + q0];
            *(float4*)&a[4] = *(float4*)&sQt[d * 68 + q0 + 4];
            *(float4*)&bb[0] = *(float4*)&sKt[d * 260 + kk0];
            *(float4*)&bb[4] = *(float4*)&sKt[d * 260 + kk0 + 4];
#pragma unroll
            for (int i = 0; i < 8; i++)
#pragma unroll
                for (int j = 0; j < 8; j++) acc[i][j] += bb[i] * a[j];
        }
#pragma unroll
        for (int i = 0; i < 8; i++)
#pragma unroll
            for (int j = 0; j < 8; j += 4) {
                float4 v = make_float4(acc[i][j] * 0.125f, acc[i][j + 1] * 0.125f,
                                       acc[i][j + 2] * 0.125f, acc[i][j + 3] * 0.125f);
                *(float4*)&sS[(kk0 + i) * 68 + q0 + j] = v;
            }
    }
    __syncthreads();
    {
        int w = t >> 5, lane = t & 31;
#pragma unroll
        for (int qq = 0; qq < 8; qq++) {
            int q = w * 8 + qq;
            float vals[8];
#pragma unroll
            for (int j = 0; j < 8; j++) vals[j] = sS[(lane + j * 32) * 68 + q];
            float m = vals[0];
#pragma unroll
            for (int j = 1; j < 8; j++) m = fmaxf(m, vals[j]);
            for (int o = 16; o; o >>= 1) m = fmaxf(m, __shfl_xor_sync(~0u, m, o));
            float sum = 0.f;
#pragma unroll
            for (int j = 0; j < 8; j++) { vals[j] = __expf(vals[j] - m); sum += vals[j]; }
            for (int o = 16; o; o >>= 1) sum += __shfl_xor_sync(~0u, sum, o);
            float inv = 1.f / sum;
#pragma unroll
            for (int j = 0; j < 8; j++) sS[(lane + j * 32) * 68 + q] = vals[j] * inv;
        }
    }
    __syncthreads();
    for (int u = t; u < 16384; u += 256) sKt[u] = g_scratch[OFF_V + kbase + u];
    __syncthreads();
    {
        int pq = (t >> 4) * 4, pd = (t & 15) * 4;
        float o[4][4];
#pragma unroll
        for (int i = 0; i < 4; i++)
#pragma unroll
            for (int j = 0; j < 4; j++) o[i][j] = 0.f;
        for (int kk = 0; kk < 256; kk++) {
            float a[4], bb[4];
            *(float4*)&a[0] = *(float4*)&sS[kk * 68 + pq];
            *(float4*)&bb[0] = *(float4*)&sKt[kk * 64 + pd];
#pragma unroll
            for (int i = 0; i < 4; i++)
#pragma unroll
                for (int j = 0; j < 4; j++) o[i][j] += a[i] * bb[j];
        }
#pragma unroll
        for (int i = 0; i < 4; i++) {
            float4 v = make_float4(o[i][0], o[i][1], o[i][2], o[i][3]);
            *(float4*)&g_scratch[OFF_SOUT + qbase + (size_t)(pq + i) * 64 + pd] = v;
        }
    }
}

// ---------------- gates ----------------
__global__ void k_gates(const float* __restrict__ Wg, const float* __restrict__ bgv) {
    int r = blockIdx.x;
    int t = threadIdx.x;          // 128
    __shared__ float sx[512];
    for (int u = t; u < 512; u += 128) sx[u] = g_scratch[OFF_INP + (size_t)r * 512 + u];
    __syncthreads();
    int w = t >> 5, lane = t & 31;
    for (int o = w; o < 24; o += 4) {
        float acc = 0.f;
        for (int kk = lane; kk < 512; kk += 32) acc += sx[kk] * Wg[(size_t)kk * 24 + o];
        for (int off = 16; off; off >>= 1) acc += __shfl_xor_sync(~0u, acc, off);
        if (lane == 0)
            g_scratch[OFF_GATES + (size_t)r * 24 + o] = 1.f / (1.f + __expf(-(acc + bgv[o])));
    }
}

// ---------------- combine ----------------
__global__ void k_combine() {
    int idx = blockIdx.x * blockDim.x + threadIdx.x;
    if (idx >= 4096 * 512) return;
    int d = idx & 63;
    int hh = (idx >> 6) & 7;
    int ri = idx >> 9;
    int b = ri >> 11, i = ri & 2047;
    size_t hidx = (((size_t)(b * 8 + hh) * 2048 + i) * 64 + d);
    const float* gg = g_scratch + OFF_GATES + (size_t)ri * 24 + hh * 3;
    g_scratch[OFF_COMB + idx] = gg[0] * g_scratch[OFF_COUT + hidx] +
                                gg[1] * g_scratch[OFF_FOUT + hidx] +
                                gg[2] * g_scratch[OFF_SOUT + hidx];
}

// ---------------- host ----------------
extern "C" void kernel_launch(void* const* d_in, const int* in_sizes, int n_in,
                              void* d_out, int out_size) {
    const float* x     = (const float*)d_in[0];
    const float* pos   = (const float*)d_in[1];
    const float* pe_W  = (const float*)d_in[2];
    const float* pe_b  = (const float*)d_in[3];
    const float* nsc   = (const float*)d_in[4];
    const float* Wqkv  = (const float*)d_in[5];
    const float* k_pos = (const float*)d_in[6];
    const float* v_pos = (const float*)d_in[7];
    const float* kcW1  = (const float*)d_in[8];
    const float* kcb1  = (const float*)d_in[9];
    const float* kcW2  = (const float*)d_in[10];
    const float* kcb2  = (const float*)d_in[11];
    const float* vcW1  = (const float*)d_in[12];
    const float* vcb1  = (const float*)d_in[13];
    const float* vcW2  = (const float*)d_in[14];
    const float* vcb2  = (const float*)d_in[15];
    const float* mem_k = (const float*)d_in[16];
    const float* mem_v = (const float*)d_in[17];
    const float* Wg    = (const float*)d_in[18];
    const float* bgv   = (const float*)d_in[19];
    const float* Wo    = (const float*)d_in[20];
    float* out = (float*)d_out;

    float* S = nullptr;
    cudaGetSymbolAddress((void**)&S, g_scratch);

    cudaFuncSetAttribute(k_fine, cudaFuncAttributeMaxDynamicSharedMemorySize, FINE_SMEM);
    cudaFuncSetAttribute(k_slide, cudaFuncAttributeMaxDynamicSharedMemorySize, SLIDE_SMEM);

    k_posmean<<<64, 64>>>(pos);
    k_pe_norm<<<4096, 256>>>(x, pos, pe_W, pe_b, nsc);

    // qkv = inp @ Wqkv : M=4096 N=768 K=512
    k_mgemm<<<dim3(6, 32, 1), 256>>>(S + OFF_INP, Wqkv, S + OFF_QKV,
                                     S + OFF_INP, Wqkv, S + OFF_QKV, 768, 512, 512, 1);
    k_split_rope<<<4096, 384>>>();
    k_buildmats<<<(128 * 4096 + 255) / 256, 256>>>(k_pos, v_pos);

    // fused kc1+vc1, split-K 4: M=128 N=4096 K=4096
    k_mgemm<<<dim3(32, 1, 8), 256>>>(S + OFF_KBM, kcW1, S + OFF_PART,
                                     S + OFF_VBM, vcW1, S + OFF_PART + 2097152,
                                     4096, 4096, 1024, 4);
    k_c1red<<<1024, 256>>>(kcb1, vcb1);
    k_c2<<<256, 256>>>(kcW2, kcb2, vcW2, vcb2);
    k_pack<<<(8448 + 255) / 256, 256>>>(mem_k, mem_v);

    k_coarse<<<8192, 128>>>();
    k_topk<<<32, 256>>>();
    k_fine<<<8192, 256, FINE_SMEM>>>();
    k_slide<<<512, 256, SLIDE_SMEM>>>();
    k_gates<<<4096, 128>>>(Wg, bgv);
    k_combine<<<(4096 * 512 + 255) / 256, 256>>>();

    // out = comb @ Wo : M=4096 N=512 K=512
    k_mgemm<<<dim3(4, 32, 1), 256>>>(S + OFF_COMB, Wo, out,
                                     S + OFF_COMB, Wo, out, 512, 512, 512, 1);
}

// round 6
// speedup vs baseline: 2.3848x; 1.0862x over previous
#include <cuda_runtime.h>
#include <cuda_bf16.h>
#include <math.h>
#include <stdint.h>

// ---------------- scratch layout (floats) ----------------
#define OFF_INP     0ul
#define OFF_QKV     2097152ul
#define OFF_Q       5242880ul
#define OFF_K       7340032ul
#define OFF_KR      7864320ul
#define OFF_V       8388608ul
#define OFF_KBM     8912896ul
#define OFF_VBM     9437184ul
#define OFF_KHID    9961472ul
#define OFF_VHID   10485760ul
#define OFF_CKRAW  11010048ul
#define OFF_CVRAW  11018240ul
#define OFF_CK     11026432ul
#define OFF_CV     11034880ul
#define OFF_COUT   11043328ul
#define OFF_FOUT   13140480ul
#define OFF_SOUT   15237632ul
#define OFF_IMP    17334784ul
#define OFF_SELVAL 17596928ul
#define OFF_GATES  17613312ul
#define OFF_COMB   17711616ul
#define OFF_PM     19808768ul
#define OFF_PART   19808960ul   /* 2 comps x 4 chunks x 128 x 4096 */
#define SCRATCH_SZ 24003264ul

__device__ float g_scratch[SCRATCH_SZ];
__device__ int   g_selidx[2 * 2 * 2048 * 2];

// ---------------- dummy (shifts ncu capture slot to k_mgemm) ----------------
__global__ void k_dummy() {}

// ================= warp-MMA helpers (sm_80+, valid on base sm_100) ============
__device__ __forceinline__ uint32_t smem_u32(const void* p) {
    uint32_t a;
    asm("{ .reg .u64 tmp; cvta.to.shared.u64 tmp, %1; cvt.u32.u64 %0, tmp; }"
        : "=r"(a) : "l"(p));
    return a;
}
__device__ __forceinline__ void ldsm_x4(uint32_t& r0, uint32_t& r1, uint32_t& r2, uint32_t& r3,
                                        uint32_t addr) {
    asm volatile("ldmatrix.sync.aligned.m8n8.x4.shared.b16 {%0,%1,%2,%3}, [%4];"
                 : "=r"(r0), "=r"(r1), "=r"(r2), "=r"(r3) : "r"(addr));
}
__device__ __forceinline__ void ldsm_x4t(uint32_t& r0, uint32_t& r1, uint32_t& r2, uint32_t& r3,
                                         uint32_t addr) {
    asm volatile("ldmatrix.sync.aligned.m8n8.x4.trans.shared.b16 {%0,%1,%2,%3}, [%4];"
                 : "=r"(r0), "=r"(r1), "=r"(r2), "=r"(r3) : "r"(addr));
}
__device__ __forceinline__ void mma16816(float* c, uint32_t a0, uint32_t a1, uint32_t a2,
                                         uint32_t a3, uint32_t b0, uint32_t b1) {
    asm volatile("mma.sync.aligned.m16n8k16.row.col.f32.bf16.bf16.f32 "
                 "{%0,%1,%2,%3}, {%4,%5,%6,%7}, {%8,%9}, {%0,%1,%2,%3};"
                 : "+f"(c[0]), "+f"(c[1]), "+f"(c[2]), "+f"(c[3])
                 : "r"(a0), "r"(a1), "r"(a2), "r"(a3), "r"(b0), "r"(b1));
}
// truncation split: hi = top-16-bits of fp32 (exact bf16), lo = (x-hi) rounded.
// hi-pack via 1 PRMT, lo-pack via 1 cvt.rn.bf16x2.
__device__ __forceinline__ void bf_split_pack(float x0, float x1, uint32_t& hp, uint32_t& lp) {
    uint32_t u0 = __float_as_uint(x0), u1 = __float_as_uint(x1);
    hp = __byte_perm(u0, u1, 0x7632);
    float l0 = x0 - __uint_as_float(u0 & 0xFFFF0000u);
    float l1 = x1 - __uint_as_float(u1 & 0xFFFF0000u);
    asm("cvt.rn.bf16x2.f32 %0, %1, %2;" : "=r"(lp) : "f"(l1), "f"(l0));
}

// ======== bf16x3 MMA GEMM: C[M x N] = A[M x K] @ B[K x N], dual-job + split-K ====
// grid (N/128, M/128, npairs*nchunks). z -> comp=z/nchunks, chunk=z%nchunks.
// Partials land at chunk * gridDim.y*128*N (raw, no bias/relu).
#define APAD 40
#define BPAD 136
__global__ void __launch_bounds__(256)
k_mgemm(const float* __restrict__ A0, const float* __restrict__ B0, float* __restrict__ C0,
        const float* __restrict__ A1, const float* __restrict__ B1, float* __restrict__ C1,
        int N, int K, int klen, int nchunks) {
    __shared__ __align__(16) uint16_t sAhi[128 * APAD];
    __shared__ __align__(16) uint16_t sAlo[128 * APAD];
    __shared__ __align__(16) uint16_t sBhi[32 * BPAD];
    __shared__ __align__(16) uint16_t sBlo[32 * BPAD];
    int z = blockIdx.z;
    int comp = z / nchunks, chunk = z - comp * nchunks;
    const float* A = comp ? A1 : A0;
    const float* B = comp ? B1 : B0;
    float* C = (comp ? C1 : C0) + (size_t)chunk * gridDim.y * 128 * N;
    int kstart = chunk * klen;
    int t = threadIdx.x, wid = t >> 5, lane = t & 31;
    int bx = blockIdx.x, by = blockIdx.y;
    int warp_m = wid >> 2, warp_n = wid & 3;   // 2 x 4

    float acc[4][4][4];
#pragma unroll
    for (int mt = 0; mt < 4; mt++)
#pragma unroll
        for (int nt = 0; nt < 4; nt++)
#pragma unroll
            for (int e = 0; e < 4; e++) acc[mt][nt][e] = 0.f;

    uint32_t a_hi_base = smem_u32(sAhi), a_lo_base = smem_u32(sAlo);
    uint32_t b_hi_base = smem_u32(sBhi), b_lo_base = smem_u32(sBlo);
    int a_row = (lane & 15), a_kc8 = 8 * (lane >> 4);
    int b_krow = (lane & 15), b_n8 = 8 * (lane >> 4);

    int nchunk32 = klen / 32;
    const float* Ab = A + (size_t)(by * 128) * K + kstart;
    const float* Bb = B + (size_t)kstart * N + bx * 128;

    // register prefetch of chunk 0
    float2 ra[8], rb[8];
#pragma unroll
    for (int p = 0; p < 8; p++) {
        int u = t + p * 256;
        ra[p] = *(const float2*)&Ab[(size_t)(u >> 4) * K + (u & 15) * 2];
    }
#pragma unroll
    for (int p = 0; p < 8; p++) {
        int u = t + p * 256;
        rb[p] = *(const float2*)&Bb[(size_t)(u >> 6) * N + (u & 63) * 2];
    }

    for (int c = 0; c < nchunk32; c++) {
        // convert current regs -> smem
#pragma unroll
        for (int p = 0; p < 8; p++) {
            int u = t + p * 256;
            uint32_t hp, lp;
            bf_split_pack(ra[p].x, ra[p].y, hp, lp);
            *(uint32_t*)&sAhi[(u >> 4) * APAD + (u & 15) * 2] = hp;
            *(uint32_t*)&sAlo[(u >> 4) * APAD + (u & 15) * 2] = lp;
        }
#pragma unroll
        for (int p = 0; p < 8; p++) {
            int u = t + p * 256;
            uint32_t hp, lp;
            bf_split_pack(rb[p].x, rb[p].y, hp, lp);
            *(uint32_t*)&sBhi[(u >> 6) * BPAD + (u & 63) * 2] = hp;
            *(uint32_t*)&sBlo[(u >> 6) * BPAD + (u & 63) * 2] = lp;
        }
        __syncthreads();
        // issue next-chunk loads; they complete during the MMA phase
        if (c + 1 < nchunk32) {
#pragma unroll
            for (int p = 0; p < 8; p++) {
                int u = t + p * 256;
                ra[p] = *(const float2*)&Ab[(size_t)(u >> 4) * K + (c + 1) * 32 + (u & 15) * 2];
            }
#pragma unroll
            for (int p = 0; p < 8; p++) {
                int u = t + p * 256;
                rb[p] = *(const float2*)&Bb[(size_t)((c + 1) * 32 + (u >> 6)) * N + (u & 63) * 2];
            }
        }
#pragma unroll
        for (int ks = 0; ks < 2; ks++) {
            uint32_t ahi[4][4], alo[4][4], bhi[4][2], blo[4][2];
#pragma unroll
            for (int mt = 0; mt < 4; mt++) {
                int off = (warp_m * 64 + mt * 16 + a_row) * APAD + ks * 16 + a_kc8;
                ldsm_x4(ahi[mt][0], ahi[mt][1], ahi[mt][2], ahi[mt][3], a_hi_base + off * 2);
                ldsm_x4(alo[mt][0], alo[mt][1], alo[mt][2], alo[mt][3], a_lo_base + off * 2);
            }
#pragma unroll
            for (int nt2 = 0; nt2 < 2; nt2++) {
                int off = (ks * 16 + b_krow) * BPAD + warp_n * 32 + nt2 * 16 + b_n8;
                ldsm_x4t(bhi[nt2 * 2][0], bhi[nt2 * 2][1], bhi[nt2 * 2 + 1][0],
                         bhi[nt2 * 2 + 1][1], b_hi_base + off * 2);
                ldsm_x4t(blo[nt2 * 2][0], blo[nt2 * 2][1], blo[nt2 * 2 + 1][0],
                         blo[nt2 * 2 + 1][1], b_lo_base + off * 2);
            }
#pragma unroll
            for (int mt = 0; mt < 4; mt++)
#pragma unroll
                for (int nt = 0; nt < 4; nt++) {
                    mma16816(acc[mt][nt], ahi[mt][0], ahi[mt][1], ahi[mt][2], ahi[mt][3],
                             bhi[nt][0], bhi[nt][1]);
                    mma16816(acc[mt][nt], ahi[mt][0], ahi[mt][1], ahi[mt][2], ahi[mt][3],
                             blo[nt][0], blo[nt][1]);
                    mma16816(acc[mt][nt], alo[mt][0], alo[mt][1], alo[mt][2], alo[mt][3],
                             bhi[nt][0], bhi[nt][1]);
                }
        }
        __syncthreads();
    }
    // epilogue: direct float2 stores
    int g = lane >> 2, tid4 = lane & 3;
#pragma unroll
    for (int mt = 0; mt < 4; mt++) {
        int row0 = by * 128 + warp_m * 64 + mt * 16 + g;
#pragma unroll
        for (int nt = 0; nt < 4; nt++) {
            int col = bx * 128 + warp_n * 32 + nt * 8 + tid4 * 2;
            *(float2*)&C[(size_t)row0 * N + col] = make_float2(acc[mt][nt][0], acc[mt][nt][1]);
            *(float2*)&C[(size_t)(row0 + 8) * N + col] = make_float2(acc[mt][nt][2], acc[mt][nt][3]);
        }
    }
}

// ---------------- c1 split-K reduce + bias + relu ----------------
__global__ void k_c1red(const float* __restrict__ kcb1, const float* __restrict__ vcb1) {
    int u4 = blockIdx.x * 256 + threadIdx.x;   // 0..262143 (float4 units)
    int comp = u4 >> 17;
    int loc = u4 & 131071;                      // float4 idx within comp
    int col4 = loc & 1023;
    const float* P = g_scratch + OFF_PART + (size_t)comp * 2097152 + (size_t)loc * 4;
    float4 s0 = *(const float4*)(P);
    float4 s1 = *(const float4*)(P + 524288);
    float4 s2 = *(const float4*)(P + 1048576);
    float4 s3 = *(const float4*)(P + 1572864);
    const float* bias = comp ? vcb1 : kcb1;
    float4 b = *(const float4*)&bias[col4 * 4];
    float4 o;
    o.x = fmaxf(s0.x + s1.x + s2.x + s3.x + b.x, 0.f);
    o.y = fmaxf(s0.y + s1.y + s2.y + s3.y + b.y, 0.f);
    o.z = fmaxf(s0.z + s1.z + s2.z + s3.z + b.z, 0.f);
    o.w = fmaxf(s0.w + s1.w + s2.w + s3.w + b.w, 0.f);
    float* O = g_scratch + (comp ? OFF_VHID : OFF_KHID) + (size_t)loc * 4;
    *(float4*)O = o;
}

// ---------------- pos block means ----------------
__global__ void k_posmean(const float* __restrict__ pos) {
    int blk = blockIdx.x;
    int t = threadIdx.x;
    __shared__ float s[64 * 3];
    s[t * 3 + 0] = pos[(blk * 64 + t) * 3 + 0];
    s[t * 3 + 1] = pos[(blk * 64 + t) * 3 + 1];
    s[t * 3 + 2] = pos[(blk * 64 + t) * 3 + 2];
    __syncthreads();
    if (t < 3) {
        float sum = 0.f;
        for (int i = 0; i < 64; i++) sum += s[i * 3 + t];
        g_scratch[OFF_PM + blk * 3 + t] = sum / 64.f;
    }
}

// ---------------- PE add + RMSNorm ----------------
__global__ void k_pe_norm(const float* __restrict__ x, const float* __restrict__ pos,
                          const float* __restrict__ peW, const float* __restrict__ peb,
                          const float* __restrict__ nsc) {
    int r = blockIdx.x;
    int t = threadIdx.x;
    int blk = r >> 6;
    float r0 = pos[r * 3 + 0] - g_scratch[OFF_PM + blk * 3 + 0];
    float r1 = pos[r * 3 + 1] - g_scratch[OFF_PM + blk * 3 + 1];
    float r2 = pos[r * 3 + 2] - g_scratch[OFF_PM + blk * 3 + 2];
    int c0 = t, c1 = t + 256;
    float v0 = x[(size_t)r * 512 + c0] + r0 * peW[c0] + r1 * peW[512 + c0] + r2 * peW[1024 + c0] + peb[c0];
    float v1 = x[(size_t)r * 512 + c1] + r0 * peW[c1] + r1 * peW[512 + c1] + r2 * peW[1024 + c1] + peb[c1];
    __shared__ float red[256];
    red[t] = v0 * v0 + v1 * v1;
    __syncthreads();
    for (int s = 128; s > 0; s >>= 1) {
        if (t < s) red[t] += red[t + s];
        __syncthreads();
    }
    float rms = rsqrtf(red[0] / 512.f + 1e-6f);
    g_scratch[OFF_INP + (size_t)r * 512 + c0] = v0 * rms * nsc[c0];
    g_scratch[OFF_INP + (size_t)r * 512 + c1] = v1 * rms * nsc[c1];
}

// ---------------- c2: 128x64x4096 per compressor ----------------
__global__ void k_c2(const float* __restrict__ kcW2, const float* __restrict__ kcb2,
                     const float* __restrict__ vcW2, const float* __restrict__ vcb2) {
    int blk = blockIdx.x;              // 256 = comp*128 + row
    int comp = blk >> 7, row = blk & 127;
    const float* A = g_scratch + (comp ? OFF_VHID : OFF_KHID) + (size_t)row * 4096;
    const float* W = comp ? vcW2 : kcW2;
    const float* bias = comp ? vcb2 : kcb2;
    float* Cout = g_scratch + (comp ? OFF_CVRAW : OFF_CKRAW) + (size_t)row * 64;
    __shared__ float sa[4096];
    __shared__ float red[256];
    int t = threadIdx.x;
    for (int u = t * 4; u < 4096; u += 1024) *(float4*)&sa[u] = *(const float4*)&A[u];
    __syncthreads();
    int o = t & 63, sub = t >> 6;
    float acc = 0.f;
    const float* Wp = W + (size_t)(sub * 1024) * 64 + o;
    const float* ap = sa + sub * 1024;
#pragma unroll 4
    for (int kk = 0; kk < 1024; kk++) acc += ap[kk] * Wp[(size_t)kk * 64];
    red[t] = acc;
    __syncthreads();
    if (t < 64) Cout[t] = red[t] + red[64 + t] + red[128 + t] + red[192 + t] + bias[t];
}

// ---------------- split qkv + rope ----------------
__global__ void k_split_rope() {
    int r = blockIdx.x;
    int b = r >> 11;
    int i = r & 2047;
    int t = threadIdx.x;          // 384
    const float* qkv = g_scratch + OFF_QKV + (size_t)r * 768;
    if (t < 256) {
        int col = t * 2;
        int head = col >> 6, d = col & 63, j = d >> 1;
        float inv = powf(10000.f, -(float)j / 32.f);
        float cs, sn;
        sincosf((float)i * inv, &sn, &cs);
        float a = qkv[col], bb = qkv[col + 1];
        size_t base = (((size_t)(b * 8 + head) * 2048 + i) * 64 + d);
        g_scratch[OFF_Q + base] = a * cs - bb * sn;
        g_scratch[OFF_Q + base + 1] = bb * cs + a * sn;
    } else if (t < 320) {
        int ci = (t - 256) * 2;
        int g = ci >> 6, d = ci & 63, j = d >> 1;
        float inv = powf(10000.f, -(float)j / 32.f);
        float cs, sn;
        sincosf((float)i * inv, &sn, &cs);
        float a = qkv[512 + ci], bb = qkv[512 + ci + 1];
        size_t base = (((size_t)(b * 2 + g) * 2048 + i) * 64 + d);
        g_scratch[OFF_K + base] = a;
        g_scratch[OFF_K + base + 1] = bb;
        g_scratch[OFF_KR + base] = a * cs - bb * sn;
        g_scratch[OFF_KR + base + 1] = bb * cs + a * sn;
    } else {
        int ci = (t - 320) * 2;
        int g = ci >> 6, d = ci & 63;
        size_t base = (((size_t)(b * 2 + g) * 2048 + i) * 64 + d);
        g_scratch[OFF_V + base] = qkv[640 + ci];
        g_scratch[OFF_V + base + 1] = qkv[640 + ci + 1];
    }
}

// ---------------- build compressor input matrices ----------------
__global__ void k_buildmats(const float* __restrict__ k_pos, const float* __restrict__ v_pos) {
    int idx = blockIdx.x * blockDim.x + threadIdx.x;
    if (idx >= 128 * 4096) return;
    int row = idx >> 12, col = idx & 4095;
    int bg = row >> 5, wi = row & 31, g = bg & 1;
    int j = col >> 6, d = col & 63;
    size_t src = ((size_t)bg * 2048 + wi * 64 + j) * 64 + d;
    float pk = k_pos[(g * 64 + j) * 64 + d];
    float pv = v_pos[(g * 64 + j) * 64 + d];
    g_scratch[OFF_KBM + idx] = g_scratch[OFF_K + src] + pk;
    g_scratch[OFF_VBM + idx] = g_scratch[OFF_V + src] + pv;
}

// ---------------- pack ck/cv with mem token ----------------
__global__ void k_pack(const float* __restrict__ mem_k, const float* __restrict__ mem_v) {
    int idx = blockIdx.x * blockDim.x + threadIdx.x;
    if (idx >= 2 * 2 * 33 * 64) return;
    int d = idx & 63;
    int rest = idx >> 6;
    int j = rest % 33;
    int bg = rest / 33;
    int g = bg & 1;
    float kv, vv;
    if (j == 0) {
        kv = mem_k[g * 64 + d];
        vv = mem_v[g * 64 + d];
    } else {
        size_t s = ((size_t)bg * 32 + (j - 1)) * 64 + d;
        kv = g_scratch[OFF_CKRAW + s];
        vv = g_scratch[OFF_CVRAW + s];
    }
    g_scratch[OFF_CK + idx] = kv;
    g_scratch[OFF_CV + idx] = vv;
}

// ---------------- coarse attention + importance ----------------
__global__ void k_coarse() {
    int bi = blockIdx.x;
    int bg = bi >> 11, i = bi & 2047;
    int b = bg >> 1, g = bg & 1;
    int t = threadIdx.x;          // 128
    __shared__ float sck[33 * 64], scv[33 * 64], sq[4 * 64], sp[4 * 36];
    for (int u = t; u < 528; u += 128) {
        *(float4*)&sck[u * 4] = *(const float4*)&g_scratch[OFF_CK + (size_t)bg * 2112 + u * 4];
        *(float4*)&scv[u * 4] = *(const float4*)&g_scratch[OFF_CV + (size_t)bg * 2112 + u * 4];
    }
    for (int u = t; u < 256; u += 128) {
        int hq = u >> 6, d = u & 63;
        sq[u] = g_scratch[OFF_Q + (((size_t)(b * 8 + g * 4 + hq) * 2048 + i) * 64 + d)];
    }
    __syncthreads();
    for (int u = t; u < 132; u += 128) {
        int hq = u / 33, j = u % 33;
        float s = -1e30f;
        if (j == 0 || j * 64 <= i) {
            float acc = 0.f;
            const float4* qv = (const float4*)&sq[hq * 64];
            const float4* kv = (const float4*)&sck[j * 64];
#pragma unroll
            for (int d4 = 0; d4 < 16; d4++) {
                float4 a = qv[d4], bb = kv[d4];
                acc += a.x * bb.x + a.y * bb.y + a.z * bb.z + a.w * bb.w;
            }
            s = acc * 0.125f;
        }
        sp[hq * 36 + j] = s;
    }
    __syncthreads();
    if (t < 4) {
        float m = -1e30f;
        for (int j = 0; j < 33; j++) m = fmaxf(m, sp[t * 36 + j]);
        float sum = 0.f;
        for (int j = 0; j < 33; j++) {
            float e = __expf(sp[t * 36 + j] - m);
            sp[t * 36 + j] = e;
            sum += e;
        }
        float inv = 1.f / sum;
        for (int j = 0; j < 33; j++) sp[t * 36 + j] *= inv;
    }
    __syncthreads();
    if (t < 32) {
        g_scratch[OFF_IMP + ((size_t)bg * 2048 + i) * 32 + t] =
            0.25f * (sp[t + 1] + sp[36 + t + 1] + sp[72 + t + 1] + sp[108 + t + 1]);
    }
    for (int u = t; u < 256; u += 128) {
        int hq = u >> 6, d = u & 63;
        float acc = 0.f;
#pragma unroll
        for (int j4 = 0; j4 < 8; j4++) {
            float4 p = *(const float4*)&sp[hq * 36 + j4 * 4];
            acc += p.x * scv[(j4 * 4 + 0) * 64 + d] + p.y * scv[(j4 * 4 + 1) * 64 + d] +
                   p.z * scv[(j4 * 4 + 2) * 64 + d] + p.w * scv[(j4 * 4 + 3) * 64 + d];
        }
        acc += sp[hq * 36 + 32] * scv[32 * 64 + d];
        g_scratch[OFF_COUT + (((size_t)(b * 8 + g * 4 + hq) * 2048 + i) * 64 + d)] = acc;
    }
}

// ---------------- top-k (k=2, stable) ----------------
__global__ void k_topk() {
    int idx = blockIdx.x * blockDim.x + threadIdx.x;
    if (idx >= 8192) return;
    const float* imp = g_scratch + OFF_IMP + (size_t)idx * 32;
    int i1 = 0;
    float v1 = imp[0];
    for (int j = 1; j < 32; j++)
        if (imp[j] > v1) { v1 = imp[j]; i1 = j; }
    int i2 = -1;
    float v2 = -1e30f;
    for (int j = 0; j < 32; j++) {
        if (j == i1) continue;
        if (imp[j] > v2) { v2 = imp[j]; i2 = j; }
    }
    g_scratch[OFF_SELVAL + idx * 2 + 0] = v1;
    g_scratch[OFF_SELVAL + idx * 2 + 1] = v2;
    g_selidx[idx * 2 + 0] = i1;
    g_selidx[idx * 2 + 1] = i2;
}

// ---------------- fine gathered attention ----------------
#define FINE_SMEM ((192 * 64 * 2 + 256 + 768) * 4)
extern __shared__ float fsm[];
__global__ void k_fine() {
    float* sk = fsm;              // 192*64
    float* sv = fsm + 12288;      // 192*64
    float* sq = fsm + 24576;      // 256
    float* sp = fsm + 24832;      // 4*192
    int bi = blockIdx.x;
    int bg = bi >> 11, i = bi & 2047;
    int b = bg >> 1, g = bg & 1;
    int t = threadIdx.x;          // 256
    int own = i >> 6;
    __shared__ int blkid[3];
    __shared__ int okf[3];
    if (t < 2) {
        int si = g_selidx[bi * 2 + t];
        float sval = g_scratch[OFF_SELVAL + bi * 2 + t];
        blkid[t] = si;
        okf[t] = (sval > 0.f && si != own) ? 1 : 0;
    }
    if (t == 2) { blkid[2] = own; okf[2] = 1; }
    __syncthreads();
    size_t kbase = (size_t)bg * 2048 * 64;
    for (int u = t; u < 3072; u += 256) {          // float4 units
        int kk = u >> 4, d4 = u & 15;
        int kb = kk >> 6, j = kk & 63;
        size_t src = kbase + (size_t)(blkid[kb] * 64 + j) * 64 + d4 * 4;
        *(float4*)&sk[u * 4] = *(const float4*)&g_scratch[OFF_KR + src];
        *(float4*)&sv[u * 4] = *(const float4*)&g_scratch[OFF_V + src];
    }
    {
        int hq = t >> 6, d = t & 63;
        sq[t] = g_scratch[OFF_Q + (((size_t)(b * 8 + g * 4 + hq) * 2048 + i) * 64 + d)];
    }
    __syncthreads();
    int ilocal = i & 63;
    for (int u = t; u < 768; u += 256) {
        int hq = u / 192, kk = u % 192;
        int kb = kk >> 6, j = kk & 63;
        bool valid = (kb < 2) ? (okf[kb] != 0) : (j <= ilocal);
        float s = -1e30f;
        if (valid) {
            float acc = 0.f;
            const float4* qv = (const float4*)&sq[hq * 64];
            const float4* kv = (const float4*)&sk[kk * 64];
#pragma unroll
            for (int d4 = 0; d4 < 16; d4++) {
                float4 a = qv[d4], bb = kv[d4];
                acc += a.x * bb.x + a.y * bb.y + a.z * bb.z + a.w * bb.w;
            }
            s = acc * 0.125f;
        }
        sp[u] = s;
    }
    __syncthreads();
    int w = t >> 5, lane = t & 31;
    if (w < 4) {
        float m = -1e30f;
        for (int kk = lane; kk < 192; kk += 32) m = fmaxf(m, sp[w * 192 + kk]);
        for (int o = 16; o; o >>= 1) m = fmaxf(m, __shfl_xor_sync(~0u, m, o));
        float sum = 0.f;
        for (int kk = lane; kk < 192; kk += 32) {
            float e = __expf(sp[w * 192 + kk] - m);
            sp[w * 192 + kk] = e;
            sum += e;
        }
        for (int o = 16; o; o >>= 1) sum += __shfl_xor_sync(~0u, sum, o);
        float inv = 1.f / sum;
        for (int kk = lane; kk < 192; kk += 32) sp[w * 192 + kk] *= inv;
    }
    __syncthreads();
    {
        int hq = t >> 6, d = t & 63;
        float acc = 0.f;
#pragma unroll
        for (int kk = 0; kk < 192; kk += 4) {
            float4 p = *(const float4*)&sp[hq * 192 + kk];
            acc += p.x * sv[(kk + 0) * 64 + d] + p.y * sv[(kk + 1) * 64 + d] +
                   p.z * sv[(kk + 2) * 64 + d] + p.w * sv[(kk + 3) * 64 + d];
        }
        g_scratch[OFF_FOUT + (((size_t)(b * 8 + g * 4 + hq) * 2048 + i) * 64 + d)] = acc;
    }
}

// ---------------- sliding attention: register-tiled ----------------
#define SLIDE_SMEM ((4352 + 16640 + 17408) * 4)
extern __shared__ float ssm2[];
__global__ void k_slide() {
    float* sQt = ssm2;
    float* sKt = ssm2 + 4352;
    float* sS  = ssm2 + 4352 + 16640;
    int id = blockIdx.x;          // ((b*8+hh)*8 + tile)*4 + qc
    int qc = id & 3;
    int tile = (id >> 2) & 7;
    int hh = (id >> 5) & 7;
    int b = id >> 8;
    int g = hh >> 2;
    int t = threadIdx.x;          // 256
    size_t kbase = ((size_t)(b * 2 + g) * 2048 + (size_t)tile * 256) * 64;
    size_t qbase = (((size_t)(b * 8 + hh) * 2048) + tile * 256 + qc * 64) * 64;
    for (int u = t; u < 16384; u += 256) {
        int kk = u >> 6, d = u & 63;
        sKt[d * 260 + kk] = g_scratch[OFF_KR + kbase + u];
    }
    for (int u = t; u < 4096; u += 256) {
        int q = u >> 6, d = u & 63;
        sQt[d * 68 + q] = g_scratch[OFF_Q + qbase + u];
    }
    __syncthreads();
    {
        int q0 = (t & 7) * 8, kk0 = (t >> 3) * 8;
        float acc[8][8];
#pragma unroll
        for (int i = 0; i < 8; i++)
#pragma unroll
            for (int j = 0; j < 8; j++) acc[i][j] = 0.f;
        for (int d = 0; d < 64; d++) {
            float a[8], bb[8];
            *(float4*)&a[0] = *(float4*)&sQt[d * 68 + q0];
            *(float4*)&a[4] = *(float4*)&sQt[d * 68 + q0 + 4];
            *(float4*)&bb[0] = *(float4*)&sKt[d * 260 + kk0];
            *(float4*)&bb[4] = *(float4*)&sKt[d * 260 + kk0 + 4];
#pragma unroll
            for (int i = 0; i < 8; i++)
#pragma unroll
                for (int j = 0; j < 8; j++) acc[i][j] += bb[i] * a[j];
        }
#pragma unroll
        for (int i = 0; i < 8; i++)
#pragma unroll
            for (int j = 0; j < 8; j += 4) {
                float4 v = make_float4(acc[i][j] * 0.125f, acc[i][j + 1] * 0.125f,
                                       acc[i][j + 2] * 0.125f, acc[i][j + 3] * 0.125f);
                *(float4*)&sS[(kk0 + i) * 68 + q0 + j] = v;
            }
    }
    __syncthreads();
    {
        int w = t >> 5, lane = t & 31;
#pragma unroll
        for (int qq = 0; qq < 8; qq++) {
            int q = w * 8 + qq;
            float vals[8];
#pragma unroll
            for (int j = 0; j < 8; j++) vals[j] = sS[(lane + j * 32) * 68 + q];
            float m = vals[0];
#pragma unroll
            for (int j = 1; j < 8; j++) m = fmaxf(m, vals[j]);
            for (int o = 16; o; o >>= 1) m = fmaxf(m, __shfl_xor_sync(~0u, m, o));
            float sum = 0.f;
#pragma unroll
            for (int j = 0; j < 8; j++) { vals[j] = __expf(vals[j] - m); sum += vals[j]; }
            for (int o = 16; o; o >>= 1) sum += __shfl_xor_sync(~0u, sum, o);
            float inv = 1.f / sum;
#pragma unroll
            for (int j = 0; j < 8; j++) sS[(lane + j * 32) * 68 + q] = vals[j] * inv;
        }
    }
    __syncthreads();
    for (int u = t; u < 16384; u += 256) sKt[u] = g_scratch[OFF_V + kbase + u];
    __syncthreads();
    {
        int pq = (t >> 4) * 4, pd = (t & 15) * 4;
        float o[4][4];
#pragma unroll
        for (int i = 0; i < 4; i++)
#pragma unroll
            for (int j = 0; j < 4; j++) o[i][j] = 0.f;
        for (int kk = 0; kk < 256; kk++) {
            float a[4], bb[4];
            *(float4*)&a[0] = *(float4*)&sS[kk * 68 + pq];
            *(float4*)&bb[0] = *(float4*)&sKt[kk * 64 + pd];
#pragma unroll
            for (int i = 0; i < 4; i++)
#pragma unroll
                for (int j = 0; j < 4; j++) o[i][j] += a[i] * bb[j];
        }
#pragma unroll
        for (int i = 0; i < 4; i++) {
            float4 v = make_float4(o[i][0], o[i][1], o[i][2], o[i][3]);
            *(float4*)&g_scratch[OFF_SOUT + qbase + (size_t)(pq + i) * 64 + pd] = v;
        }
    }
}

// ---------------- gates ----------------
__global__ void k_gates(const float* __restrict__ Wg, const float* __restrict__ bgv) {
    int r = blockIdx.x;
    int t = threadIdx.x;          // 128
    __shared__ float sx[512];
    for (int u = t; u < 512; u += 128) sx[u] = g_scratch[OFF_INP + (size_t)r * 512 + u];
    __syncthreads();
    int w = t >> 5, lane = t & 31;
    for (int o = w; o < 24; o += 4) {
        float acc = 0.f;
        for (int kk = lane; kk < 512; kk += 32) acc += sx[kk] * Wg[(size_t)kk * 24 + o];
        for (int off = 16; off; off >>= 1) acc += __shfl_xor_sync(~0u, acc, off);
        if (lane == 0)
            g_scratch[OFF_GATES + (size_t)r * 24 + o] = 1.f / (1.f + __expf(-(acc + bgv[o])));
    }
}

// ---------------- combine ----------------
__global__ void k_combine() {
    int idx = blockIdx.x * blockDim.x + threadIdx.x;
    if (idx >= 4096 * 512) return;
    int d = idx & 63;
    int hh = (idx >> 6) & 7;
    int ri = idx >> 9;
    int b = ri >> 11, i = ri & 2047;
    size_t hidx = (((size_t)(b * 8 + hh) * 2048 + i) * 64 + d);
    const float* gg = g_scratch + OFF_GATES + (size_t)ri * 24 + hh * 3;
    g_scratch[OFF_COMB + idx] = gg[0] * g_scratch[OFF_COUT + hidx] +
                                gg[1] * g_scratch[OFF_FOUT + hidx] +
                                gg[2] * g_scratch[OFF_SOUT + hidx];
}

// ---------------- host ----------------
extern "C" void kernel_launch(void* const* d_in, const int* in_sizes, int n_in,
                              void* d_out, int out_size) {
    const float* x     = (const float*)d_in[0];
    const float* pos   = (const float*)d_in[1];
    const float* pe_W  = (const float*)d_in[2];
    const float* pe_b  = (const float*)d_in[3];
    const float* nsc   = (const float*)d_in[4];
    const float* Wqkv  = (const float*)d_in[5];
    const float* k_pos = (const float*)d_in[6];
    const float* v_pos = (const float*)d_in[7];
    const float* kcW1  = (const float*)d_in[8];
    const float* kcb1  = (const float*)d_in[9];
    const float* kcW2  = (const float*)d_in[10];
    const float* kcb2  = (const float*)d_in[11];
    const float* vcW1  = (const float*)d_in[12];
    const float* vcb1  = (const float*)d_in[13];
    const float* vcW2  = (const float*)d_in[14];
    const float* vcb2  = (const float*)d_in[15];
    const float* mem_k = (const float*)d_in[16];
    const float* mem_v = (const float*)d_in[17];
    const float* Wg    = (const float*)d_in[18];
    const float* bgv   = (const float*)d_in[19];
    const float* Wo    = (const float*)d_in[20];
    float* out = (float*)d_out;

    float* S = nullptr;
    cudaGetSymbolAddress((void**)&S, g_scratch);

    cudaFuncSetAttribute(k_fine, cudaFuncAttributeMaxDynamicSharedMemorySize, FINE_SMEM);
    cudaFuncSetAttribute(k_slide, cudaFuncAttributeMaxDynamicSharedMemorySize, SLIDE_SMEM);

    k_dummy<<<1, 32>>>();     // shifts ncu capture slot: slot-4 becomes k_mgemm(qkv)
    k_posmean<<<64, 64>>>(pos);
    k_pe_norm<<<4096, 256>>>(x, pos, pe_W, pe_b, nsc);

    // qkv = inp @ Wqkv : M=4096 N=768 K=512
    k_mgemm<<<dim3(6, 32, 1), 256>>>(S + OFF_INP, Wqkv, S + OFF_QKV,
                                     S + OFF_INP, Wqkv, S + OFF_QKV, 768, 512, 512, 1);
    k_split_rope<<<4096, 384>>>();
    k_buildmats<<<(128 * 4096 + 255) / 256, 256>>>(k_pos, v_pos);

    // fused kc1+vc1, split-K 4: M=128 N=4096 K=4096
    k_mgemm<<<dim3(32, 1, 8), 256>>>(S + OFF_KBM, kcW1, S + OFF_PART,
                                     S + OFF_VBM, vcW1, S + OFF_PART + 2097152,
                                     4096, 4096, 1024, 4);
    k_c1red<<<1024, 256>>>(kcb1, vcb1);
    k_c2<<<256, 256>>>(kcW2, kcb2, vcW2, vcb2);
    k_pack<<<(8448 + 255) / 256, 256>>>(mem_k, mem_v);

    k_coarse<<<8192, 128>>>();
    k_topk<<<32, 256>>>();
    k_fine<<<8192, 256, FINE_SMEM>>>();
    k_slide<<<512, 256, SLIDE_SMEM>>>();
    k_gates<<<4096, 128>>>(Wg, bgv);
    k_combine<<<(4096 * 512 + 255) / 256, 256>>>();

    // out = comb @ Wo : M=4096 N=512 K=512
    k_mgemm<<<dim3(4, 32, 1), 256>>>(S + OFF_COMB, Wo, out,
                                     S + OFF_COMB, Wo, out, 512, 512, 512, 1);
}